// round 1
// baseline (speedup 1.0000x reference)
#include <cuda_runtime.h>
#include <math.h>
#include <stdint.h>

#define BB   2
#define SS   2048
#define DD   2048
#define HQ   32
#define HKV  8
#define DH   64

// Scratch (allocation-free rule: __device__ globals)
__device__ float g_Q[(size_t)BB * HQ  * SS * DH];   // 33.5 MB  [b][h][s][d]
__device__ float g_K[(size_t)BB * HKV * SS * DH];   //  8.4 MB
__device__ float g_V[(size_t)BB * HKV * SS * DH];   //  8.4 MB
__device__ float g_O[(size_t)BB * SS * DD];         // 33.5 MB  [b][s][h*64+d]

// ---------------------------------------------------------------------------
// SGEMM: C[M,N] = X[M,K] @ W[N,K]^T,  K=2048, tiles 128x128x16, 256 thr, 8x8/thr
// HEAD_LAYOUT=true: write to [b][h][s][d] (h = n/64, d = n%64, H = N/64)
// HEAD_LAYOUT=false: plain row-major [M][N]
// ---------------------------------------------------------------------------
template <bool HEAD_LAYOUT>
__global__ __launch_bounds__(256)
void sgemm_wt(const float* __restrict__ X, const float* __restrict__ W,
              float* __restrict__ dst, int N)
{
    const int K = 2048;
    __shared__ __align__(16) float As[16][128];
    __shared__ __align__(16) float Bs[16][128];

    const int tid = threadIdx.x;
    const int m0  = blockIdx.y * 128;
    const int n0  = blockIdx.x * 128;
    const int tx  = tid & 15;
    const int ty  = tid >> 4;

    float acc[8][8];
#pragma unroll
    for (int i = 0; i < 8; ++i)
#pragma unroll
        for (int j = 0; j < 8; ++j) acc[i][j] = 0.f;

    for (int k0 = 0; k0 < K; k0 += 16) {
#pragma unroll
        for (int l = 0; l < 2; ++l) {
            int f   = tid + 256 * l;        // float4 id, 0..511
            int row = f >> 2;               // 0..127
            int kc  = (f & 3) * 4;          // 0,4,8,12
            float4 va = *reinterpret_cast<const float4*>(
                &X[(size_t)(m0 + row) * K + k0 + kc]);
            As[kc + 0][row] = va.x; As[kc + 1][row] = va.y;
            As[kc + 2][row] = va.z; As[kc + 3][row] = va.w;
            float4 vb = *reinterpret_cast<const float4*>(
                &W[(size_t)(n0 + row) * K + k0 + kc]);
            Bs[kc + 0][row] = vb.x; Bs[kc + 1][row] = vb.y;
            Bs[kc + 2][row] = vb.z; Bs[kc + 3][row] = vb.w;
        }
        __syncthreads();

#pragma unroll
        for (int kk = 0; kk < 16; ++kk) {
            float a[8], b[8];
            *reinterpret_cast<float4*>(&a[0]) =
                *reinterpret_cast<const float4*>(&As[kk][ty * 4]);
            *reinterpret_cast<float4*>(&a[4]) =
                *reinterpret_cast<const float4*>(&As[kk][64 + ty * 4]);
            *reinterpret_cast<float4*>(&b[0]) =
                *reinterpret_cast<const float4*>(&Bs[kk][tx * 4]);
            *reinterpret_cast<float4*>(&b[4]) =
                *reinterpret_cast<const float4*>(&Bs[kk][64 + tx * 4]);
#pragma unroll
            for (int i = 0; i < 8; ++i)
#pragma unroll
                for (int j = 0; j < 8; ++j)
                    acc[i][j] += a[i] * b[j];
        }
        __syncthreads();
    }

    const int H = N >> 6;
#pragma unroll
    for (int i = 0; i < 8; ++i) {
        int m = m0 + ((i < 4) ? (ty * 4 + i) : (64 + ty * 4 + i - 4));
        int bidx = m / SS, s = m % SS;
#pragma unroll
        for (int j = 0; j < 8; ++j) {
            int n = n0 + ((j < 4) ? (tx * 4 + j) : (64 + tx * 4 + j - 4));
            if (HEAD_LAYOUT) {
                int h = n >> 6, d = n & 63;
                dst[((((size_t)bidx * H + h) * SS + s) << 6) + d] = acc[i][j];
            } else {
                dst[(size_t)m * N + n] = acc[i][j];
            }
        }
    }
}

// ---------------------------------------------------------------------------
// RoPE (interleaved pairs), applied in-place to [rows][64], s = row % S
// ---------------------------------------------------------------------------
__global__ void rope_kernel(float* __restrict__ P, int rows)
{
    int idx = blockIdx.x * blockDim.x + threadIdx.x;
    if (idx >= rows * 32) return;
    int row = idx >> 5;
    int i   = idx & 31;
    int s   = row & (SS - 1);
    // inv_freq = 10000^{-(2i)/64} = 2^{-(2i/64)*log2(10000)}
    float inv   = exp2f(-(float)(2 * i) * (13.287712379549449f / 64.0f));
    float theta = (float)s * inv;
    float sn, cs;
    sincosf(theta, &sn, &cs);
    float* p = P + (((size_t)row) << 6) + 2 * i;
    float x1 = p[0], x2 = p[1];
    p[0] = x1 * cs - x2 * sn;
    p[1] = x1 * sn + x2 * cs;
}

// ---------------------------------------------------------------------------
// Causal flash attention: 1 query row per thread, BM=128, BN=32, Dh=64
// grid: (S/128, HQ, B)
// ---------------------------------------------------------------------------
__global__ __launch_bounds__(128)
void flash_kernel(const float* __restrict__ Qp, const float* __restrict__ Kp,
                  const float* __restrict__ Vp, float* __restrict__ Op)
{
    __shared__ __align__(16) float Ks[32][64];
    __shared__ __align__(16) float Vs[32][64];

    const int tid = threadIdx.x;
    const int qb  = blockIdx.x * 128;
    const int h   = blockIdx.y;
    const int b   = blockIdx.z;
    const int kh  = h >> 2;               // G = 4 query heads per kv head
    const int m   = qb + tid;

    const float* qrow = Qp + ((((size_t)b * HQ + h) * SS + m) << 6);
    float q[64];
#pragma unroll
    for (int d = 0; d < 64; d += 4) {
        float4 v = *reinterpret_cast<const float4*>(&qrow[d]);
        q[d + 0] = v.x * 0.125f;   // 1/sqrt(64)
        q[d + 1] = v.y * 0.125f;
        q[d + 2] = v.z * 0.125f;
        q[d + 3] = v.w * 0.125f;
    }

    float acc[64];
#pragma unroll
    for (int d = 0; d < 64; ++d) acc[d] = 0.f;
    float mi = -1e30f, li = 0.f;

    const float* Kbase = Kp + (((size_t)b * HKV + kh) * SS << 6);
    const float* Vbase = Vp + (((size_t)b * HKV + kh) * SS << 6);

    const int jend = qb + 128;   // causal: keys up to last query in this block
    for (int j0 = 0; j0 < jend; j0 += 32) {
#pragma unroll
        for (int l = 0; l < 4; ++l) {
            int f  = tid + 128 * l;      // float4 id, 0..511
            int j  = f >> 4;
            int dc = (f & 15) * 4;
            *reinterpret_cast<float4*>(&Ks[j][dc]) =
                *reinterpret_cast<const float4*>(&Kbase[((size_t)(j0 + j) << 6) + dc]);
            *reinterpret_cast<float4*>(&Vs[j][dc]) =
                *reinterpret_cast<const float4*>(&Vbase[((size_t)(j0 + j) << 6) + dc]);
        }
        __syncthreads();

        float p[32];
        float mt = -1e30f;
#pragma unroll 4
        for (int j = 0; j < 32; ++j) {
            float sc = 0.f;
#pragma unroll
            for (int d = 0; d < 64; ++d) sc += q[d] * Ks[j][d];
            sc = (j0 + j <= m) ? sc : -1e30f;
            p[j] = sc;
            mt = fmaxf(mt, sc);
        }

        float mnew  = fmaxf(mi, mt);
        float alpha = __expf(mi - mnew);
        li *= alpha;
#pragma unroll
        for (int d = 0; d < 64; ++d) acc[d] *= alpha;

#pragma unroll 4
        for (int j = 0; j < 32; ++j) {
            float pj = __expf(p[j] - mnew);
            li += pj;
#pragma unroll
            for (int d = 0; d < 64; ++d) acc[d] += pj * Vs[j][d];
        }
        mi = mnew;
        __syncthreads();
    }

    float invl = 1.0f / li;
    float* orow = Op + ((size_t)(b * SS + m)) * DD + h * 64;
#pragma unroll
    for (int d = 0; d < 64; d += 4) {
        float4 v;
        v.x = acc[d + 0] * invl;
        v.y = acc[d + 1] * invl;
        v.z = acc[d + 2] * invl;
        v.w = acc[d + 3] * invl;
        *reinterpret_cast<float4*>(&orow[d]) = v;
    }
}

// ---------------------------------------------------------------------------
extern "C" void kernel_launch(void* const* d_in, const int* in_sizes, int n_in,
                              void* d_out, int out_size)
{
    const float* x  = (const float*)d_in[0];
    const float* Wq = (const float*)d_in[1];
    const float* Wk = (const float*)d_in[2];
    const float* Wv = (const float*)d_in[3];
    const float* Wo = (const float*)d_in[4];
    float* out = (float*)d_out;

    float *Qd, *Kd, *Vd, *Od;
    cudaGetSymbolAddress((void**)&Qd, g_Q);
    cudaGetSymbolAddress((void**)&Kd, g_K);
    cudaGetSymbolAddress((void**)&Vd, g_V);
    cudaGetSymbolAddress((void**)&Od, g_O);

    // QKV projections (M=4096, K=2048)
    sgemm_wt<true><<<dim3(2048 / 128, 4096 / 128), 256>>>(x, Wq, Qd, 2048);
    sgemm_wt<true><<<dim3(512  / 128, 4096 / 128), 256>>>(x, Wk, Kd, 512);
    sgemm_wt<true><<<dim3(512  / 128, 4096 / 128), 256>>>(x, Wv, Vd, 512);

    // RoPE on Q and K
    {
        int rowsQ = BB * HQ * SS;
        int rowsK = BB * HKV * SS;
        rope_kernel<<<(rowsQ * 32 + 255) / 256, 256>>>(Qd, rowsQ);
        rope_kernel<<<(rowsK * 32 + 255) / 256, 256>>>(Kd, rowsK);
    }

    // Causal flash attention
    flash_kernel<<<dim3(SS / 128, HQ, BB), 128>>>(Qd, Kd, Vd, Od);

    // Output projection (M=4096, N=2048, K=2048)
    sgemm_wt<false><<<dim3(2048 / 128, 4096 / 128), 256>>>(Od, Wo, out, 2048);
}

// round 3
// speedup vs baseline: 1.6206x; 1.6206x over previous
#include <cuda_runtime.h>
#include <cuda_bf16.h>
#include <math.h>
#include <stdint.h>

#define BB   2
#define SS   2048
#define DD   2048
#define HQ   32
#define HKV  8
#define DH   64
#define KDIM 2048

// ---------------------------------------------------------------------------
// Scratch (allocation-free rule: __device__ globals)
// ---------------------------------------------------------------------------
__device__ float g_Q[(size_t)BB * HQ  * SS * DH];
__device__ float g_K[(size_t)BB * HKV * SS * DH];
__device__ float g_V[(size_t)BB * HKV * SS * DH];
__device__ float g_O[(size_t)BB * SS * DD];

__device__ __nv_bfloat16 g_Xh[(size_t)BB * SS * DD];
__device__ __nv_bfloat16 g_Xl[(size_t)BB * SS * DD];
__device__ __nv_bfloat16 g_Wqh[(size_t)HQ * DH * DD];
__device__ __nv_bfloat16 g_Wql[(size_t)HQ * DH * DD];
__device__ __nv_bfloat16 g_Wkh[(size_t)HKV * DH * DD];
__device__ __nv_bfloat16 g_Wkl[(size_t)HKV * DH * DD];
__device__ __nv_bfloat16 g_Wvh[(size_t)HKV * DH * DD];
__device__ __nv_bfloat16 g_Wvl[(size_t)HKV * DH * DD];
__device__ __nv_bfloat16 g_Woh[(size_t)DD * DD];
__device__ __nv_bfloat16 g_Wol[(size_t)DD * DD];
__device__ __nv_bfloat16 g_Oh[(size_t)BB * SS * DD];
__device__ __nv_bfloat16 g_Ol[(size_t)BB * SS * DD];

// ---------------------------------------------------------------------------
// helpers
// ---------------------------------------------------------------------------
__device__ __forceinline__ uint32_t s2u(const void* p) {
    uint32_t r;
    asm("{ .reg .u64 t; cvta.to.shared.u64 t, %1; cvt.u32.u64 %0, t; }"
        : "=r"(r) : "l"(p));
    return r;
}

#define LDM4(r, addr)                                                         \
    asm volatile("ldmatrix.sync.aligned.m8n8.x4.shared.b16 {%0,%1,%2,%3}, [%4];" \
        : "=r"((r)[0]), "=r"((r)[1]), "=r"((r)[2]), "=r"((r)[3]) : "r"(addr))

#define MMA_BF16(c, a, b0, b1)                                                \
    asm volatile("mma.sync.aligned.m16n8k16.row.col.f32.bf16.bf16.f32 "       \
        "{%0,%1,%2,%3}, {%4,%5,%6,%7}, {%8,%9}, {%0,%1,%2,%3};"               \
        : "+f"((c)[0]), "+f"((c)[1]), "+f"((c)[2]), "+f"((c)[3])              \
        : "r"((a)[0]), "r"((a)[1]), "r"((a)[2]), "r"((a)[3]), "r"(b0), "r"(b1))

#define CP_ASYNC16(dst, src)                                                  \
    asm volatile("cp.async.cg.shared.global [%0], [%1], 16;" :: "r"(dst), "l"(src))

// ---------------------------------------------------------------------------
// split fp32 -> bf16 hi/lo
// ---------------------------------------------------------------------------
__global__ void split_bf16(const float4* __restrict__ in,
                           __nv_bfloat162* __restrict__ hi,
                           __nv_bfloat162* __restrict__ lo, int n4)
{
    int i = blockIdx.x * blockDim.x + threadIdx.x;
    if (i >= n4) return;
    float4 a = in[i];
    __nv_bfloat16 h0 = __float2bfloat16(a.x);
    __nv_bfloat16 h1 = __float2bfloat16(a.y);
    __nv_bfloat16 h2 = __float2bfloat16(a.z);
    __nv_bfloat16 h3 = __float2bfloat16(a.w);
    __nv_bfloat16 l0 = __float2bfloat16(a.x - __bfloat162float(h0));
    __nv_bfloat16 l1 = __float2bfloat16(a.y - __bfloat162float(h1));
    __nv_bfloat16 l2 = __float2bfloat16(a.z - __bfloat162float(h2));
    __nv_bfloat16 l3 = __float2bfloat16(a.w - __bfloat162float(h3));
    hi[2 * i + 0] = __nv_bfloat162(h0, h1);
    hi[2 * i + 1] = __nv_bfloat162(h2, h3);
    lo[2 * i + 0] = __nv_bfloat162(l0, l1);
    lo[2 * i + 1] = __nv_bfloat162(l2, l3);
}

// ---------------------------------------------------------------------------
// bf16 3-term mma.sync GEMM: C[M,N] = A[M,K]@B[N,K]^T, K=2048
// CTA tile 128x128x32, 8 warps (warp tile 32x64), 2-stage cp.async pipeline
// smem per stage: Ah/Al/Bh/Bl, each 128 rows x 40 bf16 (80B padded) = 10240 B
// ---------------------------------------------------------------------------
#define ROWB   80
#define MATB   10240
#define STAGEB 40960
#define KITERS (KDIM / 32)

template <bool HEAD_LAYOUT>
__global__ __launch_bounds__(256)
void mma_gemm(const __nv_bfloat16* __restrict__ Ah_g,
              const __nv_bfloat16* __restrict__ Al_g,
              const __nv_bfloat16* __restrict__ Bh_g,
              const __nv_bfloat16* __restrict__ Bl_g,
              float* __restrict__ dst, int N)
{
    extern __shared__ __align__(128) char smem[];
    const uint32_t sb = s2u(smem);

    const int tid  = threadIdx.x;
    const int lane = tid & 31;
    const int w    = tid >> 5;
    const int wm   = w & 3;        // 4 warps along M
    const int wn   = w >> 2;       // 2 warps along N
    const int m0   = blockIdx.y * 128;
    const int n0   = blockIdx.x * 128;

    // cp.async source row pointers per (i) chunk: i>>1 selects matrix
    const __nv_bfloat16* srcs[4] = { Ah_g, Al_g, Bh_g, Bl_g };
    const int rowbase[4] = { m0, m0, n0, n0 };

    auto load_stage = [&](int s, int k0) {
#pragma unroll
        for (int i = 0; i < 8; ++i) {
            const int mat = i >> 1;
            const int rem = ((i & 1) << 8) + tid;   // 0..511
            const int row = rem >> 2;
            const int seg = rem & 3;
            uint32_t d = sb + s * STAGEB + mat * MATB + row * ROWB + seg * 16;
            const __nv_bfloat16* p =
                srcs[mat] + (size_t)(rowbase[mat] + row) * KDIM + k0 + seg * 8;
            CP_ASYNC16(d, p);
        }
        asm volatile("cp.async.commit_group;");
    };

    float c[2][8][4];
#pragma unroll
    for (int i = 0; i < 2; ++i)
#pragma unroll
        for (int j = 0; j < 8; ++j)
#pragma unroll
            for (int r = 0; r < 4; ++r) c[i][j][r] = 0.f;

    // per-lane ldmatrix byte offsets (within a matrix block)
    const uint32_t a_off =
        (uint32_t)((wm * 32 + (lane & 15)) * ROWB + (lane >> 4) * 16);
    const uint32_t b_off =
        (uint32_t)((wn * 64 + (lane >> 4) * 8 + (lane & 7)) * ROWB +
                   ((lane >> 3) & 1) * 16);

    load_stage(0, 0);

    for (int it = 0; it < KITERS; ++it) {
        if (it + 1 < KITERS) {
            load_stage((it + 1) & 1, (it + 1) * 32);
            asm volatile("cp.async.wait_group 1;");
        } else {
            asm volatile("cp.async.wait_group 0;");
        }
        __syncthreads();

        const uint32_t st = sb + (it & 1) * STAGEB;
#pragma unroll
        for (int kk = 0; kk < 2; ++kk) {
            const uint32_t koff = kk * 32;   // 16 bf16 = 32 bytes
            uint32_t ah[2][4], al[2][4], bh[4][4], bl[4][4];
#pragma unroll
            for (int i = 0; i < 2; ++i) {
                LDM4(ah[i], st + 0    + a_off + i * (16 * ROWB) + koff);
                LDM4(al[i], st + MATB + a_off + i * (16 * ROWB) + koff);
            }
#pragma unroll
            for (int j2 = 0; j2 < 4; ++j2) {
                LDM4(bh[j2], st + 2 * MATB + b_off + j2 * (16 * ROWB) + koff);
                LDM4(bl[j2], st + 3 * MATB + b_off + j2 * (16 * ROWB) + koff);
            }
#pragma unroll
            for (int i = 0; i < 2; ++i)
#pragma unroll
                for (int j = 0; j < 8; ++j) {
                    const uint32_t* bhp = &bh[j >> 1][(j & 1) * 2];
                    const uint32_t* blp = &bl[j >> 1][(j & 1) * 2];
                    MMA_BF16(c[i][j], ah[i], bhp[0], bhp[1]);
                    MMA_BF16(c[i][j], ah[i], blp[0], blp[1]);
                    MMA_BF16(c[i][j], al[i], bhp[0], bhp[1]);
                }
        }
        __syncthreads();
    }

    // epilogue
    const int H = N >> 6;
#pragma unroll
    for (int i = 0; i < 2; ++i) {
        const int r0 = m0 + wm * 32 + i * 16 + (lane >> 2);
#pragma unroll
        for (int j = 0; j < 8; ++j) {
            const int col = n0 + wn * 64 + j * 8 + (lane & 3) * 2;
#pragma unroll
            for (int half = 0; half < 2; ++half) {
                const int row = r0 + half * 8;
                float2 v = make_float2(c[i][j][half * 2], c[i][j][half * 2 + 1]);
                if (HEAD_LAYOUT) {
                    const int bidx = row >> 11;
                    const int sRow = row & (SS - 1);
                    const int h = col >> 6, d0 = col & 63;
                    *reinterpret_cast<float2*>(
                        dst + ((((size_t)bidx * H + h) * SS + sRow) << 6) + d0) = v;
                } else {
                    *reinterpret_cast<float2*>(dst + (size_t)row * N + col) = v;
                }
            }
        }
    }
}

// ---------------------------------------------------------------------------
// RoPE (interleaved pairs), in-place on [rows][64], s = row % S
// ---------------------------------------------------------------------------
__global__ void rope_kernel(float* __restrict__ P, int rows)
{
    int idx = blockIdx.x * blockDim.x + threadIdx.x;
    if (idx >= rows * 32) return;
    int row = idx >> 5;
    int i   = idx & 31;
    int s   = row & (SS - 1);
    float inv   = exp2f(-(float)(2 * i) * (13.287712379549449f / 64.0f));
    float theta = (float)s * inv;
    float sn, cs;
    sincosf(theta, &sn, &cs);
    float* p = P + (((size_t)row) << 6) + 2 * i;
    float x1 = p[0], x2 = p[1];
    p[0] = x1 * cs - x2 * sn;
    p[1] = x1 * sn + x2 * cs;
}

// ---------------------------------------------------------------------------
// Causal flash attention (SIMT): 1 query row/thread, BM=128, BN=32, Dh=64
// ---------------------------------------------------------------------------
__global__ __launch_bounds__(128)
void flash_kernel(const float* __restrict__ Qp, const float* __restrict__ Kp,
                  const float* __restrict__ Vp, float* __restrict__ Op)
{
    __shared__ __align__(16) float Ks[32][64];
    __shared__ __align__(16) float Vs[32][64];

    const int tid = threadIdx.x;
    const int qb  = blockIdx.x * 128;
    const int h   = blockIdx.y;
    const int b   = blockIdx.z;
    const int kh  = h >> 2;
    const int m   = qb + tid;

    const float* qrow = Qp + ((((size_t)b * HQ + h) * SS + m) << 6);
    float q[64];
#pragma unroll
    for (int d = 0; d < 64; d += 4) {
        float4 v = *reinterpret_cast<const float4*>(&qrow[d]);
        q[d + 0] = v.x * 0.125f;
        q[d + 1] = v.y * 0.125f;
        q[d + 2] = v.z * 0.125f;
        q[d + 3] = v.w * 0.125f;
    }

    float acc[64];
#pragma unroll
    for (int d = 0; d < 64; ++d) acc[d] = 0.f;
    float mi = -1e30f, li = 0.f;

    const float* Kbase = Kp + (((size_t)b * HKV + kh) * SS << 6);
    const float* Vbase = Vp + (((size_t)b * HKV + kh) * SS << 6);

    const int jend = qb + 128;
    for (int j0 = 0; j0 < jend; j0 += 32) {
#pragma unroll
        for (int l = 0; l < 4; ++l) {
            int f  = tid + 128 * l;
            int j  = f >> 4;
            int dc = (f & 15) * 4;
            *reinterpret_cast<float4*>(&Ks[j][dc]) =
                *reinterpret_cast<const float4*>(&Kbase[((size_t)(j0 + j) << 6) + dc]);
            *reinterpret_cast<float4*>(&Vs[j][dc]) =
                *reinterpret_cast<const float4*>(&Vbase[((size_t)(j0 + j) << 6) + dc]);
        }
        __syncthreads();

        float p[32];
        float mt = -1e30f;
#pragma unroll 4
        for (int j = 0; j < 32; ++j) {
            float sc = 0.f;
#pragma unroll
            for (int d = 0; d < 64; ++d) sc += q[d] * Ks[j][d];
            sc = (j0 + j <= m) ? sc : -1e30f;
            p[j] = sc;
            mt = fmaxf(mt, sc);
        }

        float mnew  = fmaxf(mi, mt);
        float alpha = __expf(mi - mnew);
        li *= alpha;
#pragma unroll
        for (int d = 0; d < 64; ++d) acc[d] *= alpha;

#pragma unroll 4
        for (int j = 0; j < 32; ++j) {
            float pj = __expf(p[j] - mnew);
            li += pj;
#pragma unroll
            for (int d = 0; d < 64; ++d) acc[d] += pj * Vs[j][d];
        }
        mi = mnew;
        __syncthreads();
    }

    float invl = 1.0f / li;
    float* orow = Op + ((size_t)(b * SS + m)) * DD + h * 64;
#pragma unroll
    for (int d = 0; d < 64; d += 4) {
        float4 v;
        v.x = acc[d + 0] * invl;
        v.y = acc[d + 1] * invl;
        v.z = acc[d + 2] * invl;
        v.w = acc[d + 3] * invl;
        *reinterpret_cast<float4*>(&orow[d]) = v;
    }
}

// ---------------------------------------------------------------------------
// Host
// ---------------------------------------------------------------------------
extern "C" void kernel_launch(void* const* d_in, const int* in_sizes, int n_in,
                              void* d_out, int out_size)
{
    const float* x  = (const float*)d_in[0];
    const float* Wq = (const float*)d_in[1];
    const float* Wk = (const float*)d_in[2];
    const float* Wv = (const float*)d_in[3];
    const float* Wo = (const float*)d_in[4];
    float* out = (float*)d_out;

    float *Qd, *Kd, *Vd, *Od;
    __nv_bfloat16 *Xh, *Xl, *Wqh, *Wql, *Wkh, *Wkl, *Wvh, *Wvl, *Woh, *Wol, *Oh, *Ol;
    cudaGetSymbolAddress((void**)&Qd, g_Q);
    cudaGetSymbolAddress((void**)&Kd, g_K);
    cudaGetSymbolAddress((void**)&Vd, g_V);
    cudaGetSymbolAddress((void**)&Od, g_O);
    cudaGetSymbolAddress((void**)&Xh, g_Xh);
    cudaGetSymbolAddress((void**)&Xl, g_Xl);
    cudaGetSymbolAddress((void**)&Wqh, g_Wqh);
    cudaGetSymbolAddress((void**)&Wql, g_Wql);
    cudaGetSymbolAddress((void**)&Wkh, g_Wkh);
    cudaGetSymbolAddress((void**)&Wkl, g_Wkl);
    cudaGetSymbolAddress((void**)&Wvh, g_Wvh);
    cudaGetSymbolAddress((void**)&Wvl, g_Wvl);
    cudaGetSymbolAddress((void**)&Woh, g_Woh);
    cudaGetSymbolAddress((void**)&Wol, g_Wol);
    cudaGetSymbolAddress((void**)&Oh, g_Oh);
    cudaGetSymbolAddress((void**)&Ol, g_Ol);

    const int SMEM_DYN = 2 * STAGEB;   // 81920
    cudaFuncSetAttribute(mma_gemm<true>,  cudaFuncAttributeMaxDynamicSharedMemorySize, SMEM_DYN);
    cudaFuncSetAttribute(mma_gemm<false>, cudaFuncAttributeMaxDynamicSharedMemorySize, SMEM_DYN);

    // splits
    {
        int n;
        n = BB * SS * DD / 4;
        split_bf16<<<(n + 255) / 256, 256>>>((const float4*)x,
            (__nv_bfloat162*)Xh, (__nv_bfloat162*)Xl, n);
        n = HQ * DH * DD / 4;
        split_bf16<<<(n + 255) / 256, 256>>>((const float4*)Wq,
            (__nv_bfloat162*)Wqh, (__nv_bfloat162*)Wql, n);
        n = HKV * DH * DD / 4;
        split_bf16<<<(n + 255) / 256, 256>>>((const float4*)Wk,
            (__nv_bfloat162*)Wkh, (__nv_bfloat162*)Wkl, n);
        split_bf16<<<(n + 255) / 256, 256>>>((const float4*)Wv,
            (__nv_bfloat162*)Wvh, (__nv_bfloat162*)Wvl, n);
        n = DD * DD / 4;
        split_bf16<<<(n + 255) / 256, 256>>>((const float4*)Wo,
            (__nv_bfloat162*)Woh, (__nv_bfloat162*)Wol, n);
    }

    // QKV projections (tensor cores, 3-term bf16)
    mma_gemm<true><<<dim3(16, 32), 256, SMEM_DYN>>>(Xh, Xl, Wqh, Wql, Qd, 2048);
    mma_gemm<true><<<dim3(4,  32), 256, SMEM_DYN>>>(Xh, Xl, Wkh, Wkl, Kd, 512);
    mma_gemm<true><<<dim3(4,  32), 256, SMEM_DYN>>>(Xh, Xl, Wvh, Wvl, Vd, 512);

    // RoPE
    {
        int rowsQ = BB * HQ * SS;
        int rowsK = BB * HKV * SS;
        rope_kernel<<<(rowsQ * 32 + 255) / 256, 256>>>(Qd, rowsQ);
        rope_kernel<<<(rowsK * 32 + 255) / 256, 256>>>(Kd, rowsK);
    }

    // Flash attention (SIMT fp32)
    flash_kernel<<<dim3(SS / 128, HQ, BB), 128>>>(Qd, Kd, Vd, Od);

    // split attention output, output projection
    {
        int n = BB * SS * DD / 4;
        split_bf16<<<(n + 255) / 256, 256>>>((const float4*)Od,
            (__nv_bfloat162*)Oh, (__nv_bfloat162*)Ol, n);
    }
    mma_gemm<false><<<dim3(16, 32), 256, SMEM_DYN>>>(Oh, Ol, Woh, Wol, out, 2048);
}

// round 4
// speedup vs baseline: 3.0952x; 1.9099x over previous
#include <cuda_runtime.h>
#include <cuda_bf16.h>
#include <math.h>
#include <stdint.h>

#define BB   2
#define SS   2048
#define DD   2048
#define HQ   32
#define HKV  8
#define DH   64
#define KDIM 2048

// ---------------------------------------------------------------------------
// Scratch (allocation-free rule: __device__ globals)
// ---------------------------------------------------------------------------
__device__ float g_Q[(size_t)BB * HQ  * SS * DH];
__device__ float g_K[(size_t)BB * HKV * SS * DH];
__device__ float g_V[(size_t)BB * HKV * SS * DH];
__device__ float g_O[(size_t)BB * SS * DD];

__device__ __nv_bfloat16 g_Xh[(size_t)BB * SS * DD];
__device__ __nv_bfloat16 g_Xl[(size_t)BB * SS * DD];
__device__ __nv_bfloat16 g_Wqh[(size_t)HQ * DH * DD];
__device__ __nv_bfloat16 g_Wql[(size_t)HQ * DH * DD];
__device__ __nv_bfloat16 g_Wkh[(size_t)HKV * DH * DD];
__device__ __nv_bfloat16 g_Wkl[(size_t)HKV * DH * DD];
__device__ __nv_bfloat16 g_Wvh[(size_t)HKV * DH * DD];
__device__ __nv_bfloat16 g_Wvl[(size_t)HKV * DH * DD];
__device__ __nv_bfloat16 g_Woh[(size_t)DD * DD];
__device__ __nv_bfloat16 g_Wol[(size_t)DD * DD];
__device__ __nv_bfloat16 g_Oh[(size_t)BB * SS * DD];
__device__ __nv_bfloat16 g_Ol[(size_t)BB * SS * DD];

// bf16 hi/lo of roped Q (scaled), roped K, V — for MMA flash attention
__device__ __nv_bfloat16 g_Qbh[(size_t)BB * HQ  * SS * DH];
__device__ __nv_bfloat16 g_Qbl[(size_t)BB * HQ  * SS * DH];
__device__ __nv_bfloat16 g_Kbh[(size_t)BB * HKV * SS * DH];
__device__ __nv_bfloat16 g_Kbl[(size_t)BB * HKV * SS * DH];
__device__ __nv_bfloat16 g_Vbh[(size_t)BB * HKV * SS * DH];
__device__ __nv_bfloat16 g_Vbl[(size_t)BB * HKV * SS * DH];

// ---------------------------------------------------------------------------
// helpers
// ---------------------------------------------------------------------------
__device__ __forceinline__ uint32_t s2u(const void* p) {
    uint32_t r;
    asm("{ .reg .u64 t; cvta.to.shared.u64 t, %1; cvt.u32.u64 %0, t; }"
        : "=r"(r) : "l"(p));
    return r;
}

#define LDM4(r, addr)                                                         \
    asm volatile("ldmatrix.sync.aligned.m8n8.x4.shared.b16 {%0,%1,%2,%3}, [%4];" \
        : "=r"((r)[0]), "=r"((r)[1]), "=r"((r)[2]), "=r"((r)[3]) : "r"(addr))

#define LDM4T(r, addr)                                                        \
    asm volatile("ldmatrix.sync.aligned.m8n8.x4.trans.shared.b16 {%0,%1,%2,%3}, [%4];" \
        : "=r"((r)[0]), "=r"((r)[1]), "=r"((r)[2]), "=r"((r)[3]) : "r"(addr))

#define MMA_BF16(c, a, b0, b1)                                                \
    asm volatile("mma.sync.aligned.m16n8k16.row.col.f32.bf16.bf16.f32 "       \
        "{%0,%1,%2,%3}, {%4,%5,%6,%7}, {%8,%9}, {%0,%1,%2,%3};"               \
        : "+f"((c)[0]), "+f"((c)[1]), "+f"((c)[2]), "+f"((c)[3])              \
        : "r"((a)[0]), "r"((a)[1]), "r"((a)[2]), "r"((a)[3]), "r"(b0), "r"(b1))

#define CP_ASYNC16(dst, src)                                                  \
    asm volatile("cp.async.cg.shared.global [%0], [%1], 16;" :: "r"(dst), "l"(src))

__device__ __forceinline__ uint32_t pack_bf2(float a, float b) {
    __nv_bfloat162 t = __floats2bfloat162_rn(a, b);
    return *reinterpret_cast<uint32_t*>(&t);
}

// ---------------------------------------------------------------------------
// split fp32 -> bf16 hi/lo
// ---------------------------------------------------------------------------
__global__ void split_bf16(const float4* __restrict__ in,
                           __nv_bfloat162* __restrict__ hi,
                           __nv_bfloat162* __restrict__ lo, int n4)
{
    int i = blockIdx.x * blockDim.x + threadIdx.x;
    if (i >= n4) return;
    float4 a = in[i];
    __nv_bfloat16 h0 = __float2bfloat16(a.x);
    __nv_bfloat16 h1 = __float2bfloat16(a.y);
    __nv_bfloat16 h2 = __float2bfloat16(a.z);
    __nv_bfloat16 h3 = __float2bfloat16(a.w);
    __nv_bfloat16 l0 = __float2bfloat16(a.x - __bfloat162float(h0));
    __nv_bfloat16 l1 = __float2bfloat16(a.y - __bfloat162float(h1));
    __nv_bfloat16 l2 = __float2bfloat16(a.z - __bfloat162float(h2));
    __nv_bfloat16 l3 = __float2bfloat16(a.w - __bfloat162float(h3));
    hi[2 * i + 0] = __nv_bfloat162(h0, h1);
    hi[2 * i + 1] = __nv_bfloat162(h2, h3);
    lo[2 * i + 0] = __nv_bfloat162(l0, l1);
    lo[2 * i + 1] = __nv_bfloat162(l2, l3);
}

// ---------------------------------------------------------------------------
// fused (optional RoPE) + scale + bf16 hi/lo split, rows of 64 fp32
// ---------------------------------------------------------------------------
template <bool ROPE>
__global__ void rope_split(const float* __restrict__ src,
                           __nv_bfloat16* __restrict__ h,
                           __nv_bfloat16* __restrict__ l,
                           int rows, float scale)
{
    int idx = blockIdx.x * blockDim.x + threadIdx.x;
    if (idx >= rows * 32) return;
    int row = idx >> 5;
    int i   = idx & 31;
    float2 v = *reinterpret_cast<const float2*>(src + (((size_t)row) << 6) + 2 * i);
    float x1 = v.x, x2 = v.y;
    if (ROPE) {
        int s = row & (SS - 1);
        float inv   = exp2f(-(float)(2 * i) * (13.287712379549449f / 64.0f));
        float theta = (float)s * inv;
        float sn, cs;
        sincosf(theta, &sn, &cs);
        float y1 = x1 * cs - x2 * sn;
        float y2 = x1 * sn + x2 * cs;
        x1 = y1; x2 = y2;
    }
    x1 *= scale; x2 *= scale;
    __nv_bfloat16 h1 = __float2bfloat16(x1);
    __nv_bfloat16 h2 = __float2bfloat16(x2);
    __nv_bfloat16 l1 = __float2bfloat16(x1 - __bfloat162float(h1));
    __nv_bfloat16 l2 = __float2bfloat16(x2 - __bfloat162float(h2));
    *reinterpret_cast<__nv_bfloat162*>(h + (((size_t)row) << 6) + 2 * i) =
        __nv_bfloat162(h1, h2);
    *reinterpret_cast<__nv_bfloat162*>(l + (((size_t)row) << 6) + 2 * i) =
        __nv_bfloat162(l1, l2);
}

// ---------------------------------------------------------------------------
// bf16 3-term mma.sync GEMM: C[M,N] = A[M,K]@B[N,K]^T, K=2048 (unchanged)
// ---------------------------------------------------------------------------
#define ROWB   80
#define MATB   10240
#define STAGEB 40960
#define KITERS (KDIM / 32)

template <bool HEAD_LAYOUT>
__global__ __launch_bounds__(256)
void mma_gemm(const __nv_bfloat16* __restrict__ Ah_g,
              const __nv_bfloat16* __restrict__ Al_g,
              const __nv_bfloat16* __restrict__ Bh_g,
              const __nv_bfloat16* __restrict__ Bl_g,
              float* __restrict__ dst, int N)
{
    extern __shared__ __align__(128) char smem[];
    const uint32_t sb = s2u(smem);

    const int tid  = threadIdx.x;
    const int lane = tid & 31;
    const int w    = tid >> 5;
    const int wm   = w & 3;
    const int wn   = w >> 2;
    const int m0   = blockIdx.y * 128;
    const int n0   = blockIdx.x * 128;

    const __nv_bfloat16* srcs[4] = { Ah_g, Al_g, Bh_g, Bl_g };
    const int rowbase[4] = { m0, m0, n0, n0 };

    auto load_stage = [&](int s, int k0) {
#pragma unroll
        for (int i = 0; i < 8; ++i) {
            const int mat = i >> 1;
            const int rem = ((i & 1) << 8) + tid;
            const int row = rem >> 2;
            const int seg = rem & 3;
            uint32_t d = sb + s * STAGEB + mat * MATB + row * ROWB + seg * 16;
            const __nv_bfloat16* p =
                srcs[mat] + (size_t)(rowbase[mat] + row) * KDIM + k0 + seg * 8;
            CP_ASYNC16(d, p);
        }
        asm volatile("cp.async.commit_group;");
    };

    float c[2][8][4];
#pragma unroll
    for (int i = 0; i < 2; ++i)
#pragma unroll
        for (int j = 0; j < 8; ++j)
#pragma unroll
            for (int r = 0; r < 4; ++r) c[i][j][r] = 0.f;

    const uint32_t a_off =
        (uint32_t)((wm * 32 + (lane & 15)) * ROWB + (lane >> 4) * 16);
    const uint32_t b_off =
        (uint32_t)((wn * 64 + (lane >> 4) * 8 + (lane & 7)) * ROWB +
                   ((lane >> 3) & 1) * 16);

    load_stage(0, 0);

    for (int it = 0; it < KITERS; ++it) {
        if (it + 1 < KITERS) {
            load_stage((it + 1) & 1, (it + 1) * 32);
            asm volatile("cp.async.wait_group 1;");
        } else {
            asm volatile("cp.async.wait_group 0;");
        }
        __syncthreads();

        const uint32_t st = sb + (it & 1) * STAGEB;
#pragma unroll
        for (int kk = 0; kk < 2; ++kk) {
            const uint32_t koff = kk * 32;
            uint32_t ah[2][4], al[2][4], bh[4][4], bl[4][4];
#pragma unroll
            for (int i = 0; i < 2; ++i) {
                LDM4(ah[i], st + 0    + a_off + i * (16 * ROWB) + koff);
                LDM4(al[i], st + MATB + a_off + i * (16 * ROWB) + koff);
            }
#pragma unroll
            for (int j2 = 0; j2 < 4; ++j2) {
                LDM4(bh[j2], st + 2 * MATB + b_off + j2 * (16 * ROWB) + koff);
                LDM4(bl[j2], st + 3 * MATB + b_off + j2 * (16 * ROWB) + koff);
            }
#pragma unroll
            for (int i = 0; i < 2; ++i)
#pragma unroll
                for (int j = 0; j < 8; ++j) {
                    const uint32_t* bhp = &bh[j >> 1][(j & 1) * 2];
                    const uint32_t* blp = &bl[j >> 1][(j & 1) * 2];
                    MMA_BF16(c[i][j], ah[i], bhp[0], bhp[1]);
                    MMA_BF16(c[i][j], ah[i], blp[0], blp[1]);
                    MMA_BF16(c[i][j], al[i], bhp[0], bhp[1]);
                }
        }
        __syncthreads();
    }

    const int H = N >> 6;
#pragma unroll
    for (int i = 0; i < 2; ++i) {
        const int r0 = m0 + wm * 32 + i * 16 + (lane >> 2);
#pragma unroll
        for (int j = 0; j < 8; ++j) {
            const int col = n0 + wn * 64 + j * 8 + (lane & 3) * 2;
#pragma unroll
            for (int half = 0; half < 2; ++half) {
                const int row = r0 + half * 8;
                float2 v = make_float2(c[i][j][half * 2], c[i][j][half * 2 + 1]);
                if (HEAD_LAYOUT) {
                    const int bidx = row >> 11;
                    const int sRow = row & (SS - 1);
                    const int h = col >> 6, d0 = col & 63;
                    *reinterpret_cast<float2*>(
                        dst + ((((size_t)bidx * H + h) * SS + sRow) << 6) + d0) = v;
                } else {
                    *reinterpret_cast<float2*>(dst + (size_t)row * N + col) = v;
                }
            }
        }
    }
}

// ---------------------------------------------------------------------------
// MMA flash attention (causal, GQA): BM=64 (4 warps x 16 rows), BN=64, Dh=64
// 3-term bf16 split for both Q.K^T and P.V. grid: (S/64, HQ, B)
// smem: Qh/Ql tiles (held for whole CTA) + 2-stage {Kh,Kl,Vh,Vl} ring
// row pitch 144B (64 bf16 data + 8 bf16 pad) -> conflict-free ldmatrix
// ---------------------------------------------------------------------------
#define FROW   144
#define FTILE  9216          // 64 * 144
#define FSTAGE 36864         // 4 * FTILE
#define FSMEM  (2 * FTILE + 2 * FSTAGE)   // 92160

__global__ __launch_bounds__(128)
void flash_mma(const __nv_bfloat16* __restrict__ Qh_g,
               const __nv_bfloat16* __restrict__ Ql_g,
               const __nv_bfloat16* __restrict__ Kh_g,
               const __nv_bfloat16* __restrict__ Kl_g,
               const __nv_bfloat16* __restrict__ Vh_g,
               const __nv_bfloat16* __restrict__ Vl_g,
               float* __restrict__ Op)
{
    extern __shared__ __align__(128) char fsm[];
    const uint32_t sb = s2u(fsm);

    const int tid  = threadIdx.x;
    const int lane = tid & 31;
    const int w    = tid >> 5;
    const int qb   = blockIdx.x * 64;
    const int h    = blockIdx.y;
    const int b    = blockIdx.z;
    const int kh   = h >> 2;

    const size_t qoff  = (((size_t)b * HQ + h) * SS + qb) * 64;
    const size_t kvrow = ((size_t)b * HKV + kh) * SS;

    // ---- prologue: stage Q (hi/lo) ----
#pragma unroll
    for (int i = 0; i < 8; ++i) {
        int idx = tid + 128 * i;
        int mat = idx >> 9;
        int rem = idx & 511;
        int row = rem >> 3;
        int seg = rem & 7;
        uint32_t d = sb + mat * FTILE + row * FROW + seg * 16;
        const __nv_bfloat16* p = (mat ? Ql_g : Qh_g) + qoff + row * 64 + seg * 8;
        CP_ASYNC16(d, p);
    }
    asm volatile("cp.async.commit_group;");

    auto load_kv = [&](int s, int j0) {
        const __nv_bfloat16* srcs[4] = { Kh_g, Kl_g, Vh_g, Vl_g };
        const size_t off = (kvrow + j0) * 64;
#pragma unroll
        for (int i = 0; i < 16; ++i) {
            int idx = tid + 128 * i;
            int mat = idx >> 9;
            int rem = idx & 511;
            int row = rem >> 3;
            int seg = rem & 7;
            uint32_t d = sb + 2 * FTILE + s * FSTAGE + mat * FTILE + row * FROW + seg * 16;
            CP_ASYNC16(d, srcs[mat] + off + row * 64 + seg * 8);
        }
        asm volatile("cp.async.commit_group;");
    };

    const int nb = qb / 64 + 1;
    load_kv(0, 0);

    float o[8][4];
#pragma unroll
    for (int j = 0; j < 8; ++j)
#pragma unroll
        for (int r = 0; r < 4; ++r) o[j][r] = 0.f;
    float mi[2] = { -1e30f, -1e30f };
    float li[2] = { 0.f, 0.f };

    uint32_t qh[4][4], ql[4][4];

    const uint32_t a_off =
        (uint32_t)((w * 16 + (lane & 15)) * FROW + (lane >> 4) * 16);
    const uint32_t kb_off =
        (uint32_t)(((lane >> 4) * 8 + (lane & 7)) * FROW + ((lane >> 3) & 1) * 16);
    const uint32_t v_off =
        (uint32_t)((lane & 15) * FROW + (lane >> 4) * 16);

    const int row0 = qb + w * 16 + (lane >> 2);

    for (int it = 0; it < nb; ++it) {
        if (it + 1 < nb) {
            load_kv((it + 1) & 1, (it + 1) * 64);
            asm volatile("cp.async.wait_group 1;");
        } else {
            asm volatile("cp.async.wait_group 0;");
        }
        __syncthreads();

        if (it == 0) {
#pragma unroll
            for (int kc = 0; kc < 4; ++kc) {
                LDM4(qh[kc], sb + a_off + kc * 32);
                LDM4(ql[kc], sb + FTILE + a_off + kc * 32);
            }
        }

        const uint32_t kvb = sb + 2 * FTILE + (it & 1) * FSTAGE;
        const int j0 = it * 64;

        // ---- S = Q.K^T (3-term) ----
        float s[8][4];
#pragma unroll
        for (int j = 0; j < 8; ++j)
#pragma unroll
            for (int r = 0; r < 4; ++r) s[j][r] = 0.f;

#pragma unroll
        for (int kc = 0; kc < 4; ++kc) {
            uint32_t bh[4][4], bl[4][4];
#pragma unroll
            for (int j2 = 0; j2 < 4; ++j2) {
                LDM4(bh[j2], kvb + j2 * (16 * FROW) + kb_off + kc * 32);
                LDM4(bl[j2], kvb + FTILE + j2 * (16 * FROW) + kb_off + kc * 32);
            }
#pragma unroll
            for (int j = 0; j < 8; ++j) {
                const uint32_t* bhp = &bh[j >> 1][(j & 1) * 2];
                const uint32_t* blp = &bl[j >> 1][(j & 1) * 2];
                MMA_BF16(s[j], qh[kc], bhp[0], bhp[1]);
                MMA_BF16(s[j], qh[kc], blp[0], blp[1]);
                MMA_BF16(s[j], ql[kc], bhp[0], bhp[1]);
            }
        }

        // ---- causal mask on the diagonal block ----
        if (j0 == qb) {
#pragma unroll
            for (int j = 0; j < 8; ++j)
#pragma unroll
                for (int r = 0; r < 4; ++r) {
                    int col = j0 + j * 8 + (lane & 3) * 2 + (r & 1);
                    int row = row0 + (r >> 1) * 8;
                    if (col > row) s[j][r] = -1e30f;
                }
        }

        // ---- online softmax (two row-halves per thread) ----
#pragma unroll
        for (int h2 = 0; h2 < 2; ++h2) {
            float mt = -1e30f;
#pragma unroll
            for (int j = 0; j < 8; ++j) {
                mt = fmaxf(mt, s[j][h2 * 2]);
                mt = fmaxf(mt, s[j][h2 * 2 + 1]);
            }
            mt = fmaxf(mt, __shfl_xor_sync(0xffffffffu, mt, 1));
            mt = fmaxf(mt, __shfl_xor_sync(0xffffffffu, mt, 2));
            float mnew  = fmaxf(mi[h2], mt);
            float alpha = __expf(mi[h2] - mnew);
            mi[h2] = mnew;
            float sum = 0.f;
#pragma unroll
            for (int j = 0; j < 8; ++j) {
                float p0 = __expf(s[j][h2 * 2]     - mnew);
                float p1 = __expf(s[j][h2 * 2 + 1] - mnew);
                s[j][h2 * 2]     = p0;
                s[j][h2 * 2 + 1] = p1;
                sum += p0 + p1;
                o[j][h2 * 2]     *= alpha;
                o[j][h2 * 2 + 1] *= alpha;
            }
            sum += __shfl_xor_sync(0xffffffffu, sum, 1);
            sum += __shfl_xor_sync(0xffffffffu, sum, 2);
            li[h2] = li[h2] * alpha + sum;
        }

        // ---- P fragments (hi/lo) ----
        uint32_t ph[4][4], pl[4][4];
#pragma unroll
        for (int kc = 0; kc < 4; ++kc) {
            const int jt = 2 * kc;
#pragma unroll
            for (int r = 0; r < 4; ++r) {
                float a = s[jt + (r >> 1)][(r & 1) * 2];
                float c2 = s[jt + (r >> 1)][(r & 1) * 2 + 1];
                // reg order: r0=(row,k01), r1=(row+8,k01), r2=(row,k89), r3=(row+8,k89)
                // map: r0 <- tile jt regs 0,1 ; r1 <- tile jt regs 2,3 ;
                //      r2 <- tile jt+1 regs 0,1 ; r3 <- tile jt+1 regs 2,3
                (void)a; (void)c2;
            }
            float a0 = s[jt][0],     a1 = s[jt][1];
            float a2 = s[jt][2],     a3 = s[jt][3];
            float b0 = s[jt + 1][0], b1 = s[jt + 1][1];
            float b2 = s[jt + 1][2], b3 = s[jt + 1][3];
            ph[kc][0] = pack_bf2(a0, a1);
            ph[kc][1] = pack_bf2(a2, a3);
            ph[kc][2] = pack_bf2(b0, b1);
            ph[kc][3] = pack_bf2(b2, b3);
            __nv_bfloat162 t;
            t = *reinterpret_cast<__nv_bfloat162*>(&ph[kc][0]);
            pl[kc][0] = pack_bf2(a0 - __bfloat162float(t.x), a1 - __bfloat162float(t.y));
            t = *reinterpret_cast<__nv_bfloat162*>(&ph[kc][1]);
            pl[kc][1] = pack_bf2(a2 - __bfloat162float(t.x), a3 - __bfloat162float(t.y));
            t = *reinterpret_cast<__nv_bfloat162*>(&ph[kc][2]);
            pl[kc][2] = pack_bf2(b0 - __bfloat162float(t.x), b1 - __bfloat162float(t.y));
            t = *reinterpret_cast<__nv_bfloat162*>(&ph[kc][3]);
            pl[kc][3] = pack_bf2(b2 - __bfloat162float(t.x), b3 - __bfloat162float(t.y));
        }

        // ---- O += P.V (3-term), V via ldmatrix.trans ----
#pragma unroll
        for (int kc = 0; kc < 4; ++kc) {
#pragma unroll
            for (int np = 0; np < 4; ++np) {
                uint32_t vh4[4], vl4[4];
                uint32_t va = kvb + 2 * FTILE + kc * (16 * FROW) + v_off + np * 32;
                LDM4T(vh4, va);
                LDM4T(vl4, va + FTILE);
                MMA_BF16(o[2 * np],     ph[kc], vh4[0], vh4[1]);
                MMA_BF16(o[2 * np],     ph[kc], vl4[0], vl4[1]);
                MMA_BF16(o[2 * np],     pl[kc], vh4[0], vh4[1]);
                MMA_BF16(o[2 * np + 1], ph[kc], vh4[2], vh4[3]);
                MMA_BF16(o[2 * np + 1], ph[kc], vl4[2], vl4[3]);
                MMA_BF16(o[2 * np + 1], pl[kc], vh4[2], vh4[3]);
            }
        }

        __syncthreads();
    }

    // ---- finalize & store: g_O[b][s][h*64+d] ----
    float inv0 = 1.0f / li[0];
    float inv1 = 1.0f / li[1];
#pragma unroll
    for (int j = 0; j < 8; ++j) {
        const int col = j * 8 + (lane & 3) * 2;
        float2 v0 = make_float2(o[j][0] * inv0, o[j][1] * inv0);
        float2 v1 = make_float2(o[j][2] * inv1, o[j][3] * inv1);
        *reinterpret_cast<float2*>(
            Op + ((size_t)(b * SS + row0)) * DD + h * 64 + col) = v0;
        *reinterpret_cast<float2*>(
            Op + ((size_t)(b * SS + row0 + 8)) * DD + h * 64 + col) = v1;
    }
}

// ---------------------------------------------------------------------------
// Host
// ---------------------------------------------------------------------------
extern "C" void kernel_launch(void* const* d_in, const int* in_sizes, int n_in,
                              void* d_out, int out_size)
{
    const float* x  = (const float*)d_in[0];
    const float* Wq = (const float*)d_in[1];
    const float* Wk = (const float*)d_in[2];
    const float* Wv = (const float*)d_in[3];
    const float* Wo = (const float*)d_in[4];
    float* out = (float*)d_out;

    float *Qd, *Kd, *Vd, *Od;
    __nv_bfloat16 *Xh, *Xl, *Wqh, *Wql, *Wkh, *Wkl, *Wvh, *Wvl, *Woh, *Wol, *Oh, *Ol;
    __nv_bfloat16 *Qbh, *Qbl, *Kbh, *Kbl, *Vbh, *Vbl;
    cudaGetSymbolAddress((void**)&Qd, g_Q);
    cudaGetSymbolAddress((void**)&Kd, g_K);
    cudaGetSymbolAddress((void**)&Vd, g_V);
    cudaGetSymbolAddress((void**)&Od, g_O);
    cudaGetSymbolAddress((void**)&Xh, g_Xh);
    cudaGetSymbolAddress((void**)&Xl, g_Xl);
    cudaGetSymbolAddress((void**)&Wqh, g_Wqh);
    cudaGetSymbolAddress((void**)&Wql, g_Wql);
    cudaGetSymbolAddress((void**)&Wkh, g_Wkh);
    cudaGetSymbolAddress((void**)&Wkl, g_Wkl);
    cudaGetSymbolAddress((void**)&Wvh, g_Wvh);
    cudaGetSymbolAddress((void**)&Wvl, g_Wvl);
    cudaGetSymbolAddress((void**)&Woh, g_Woh);
    cudaGetSymbolAddress((void**)&Wol, g_Wol);
    cudaGetSymbolAddress((void**)&Oh, g_Oh);
    cudaGetSymbolAddress((void**)&Ol, g_Ol);
    cudaGetSymbolAddress((void**)&Qbh, g_Qbh);
    cudaGetSymbolAddress((void**)&Qbl, g_Qbl);
    cudaGetSymbolAddress((void**)&Kbh, g_Kbh);
    cudaGetSymbolAddress((void**)&Kbl, g_Kbl);
    cudaGetSymbolAddress((void**)&Vbh, g_Vbh);
    cudaGetSymbolAddress((void**)&Vbl, g_Vbl);

    const int SMEM_DYN = 2 * STAGEB;
    cudaFuncSetAttribute(mma_gemm<true>,  cudaFuncAttributeMaxDynamicSharedMemorySize, SMEM_DYN);
    cudaFuncSetAttribute(mma_gemm<false>, cudaFuncAttributeMaxDynamicSharedMemorySize, SMEM_DYN);
    cudaFuncSetAttribute(flash_mma, cudaFuncAttributeMaxDynamicSharedMemorySize, FSMEM);

    // splits of x and weights
    {
        int n;
        n = BB * SS * DD / 4;
        split_bf16<<<(n + 255) / 256, 256>>>((const float4*)x,
            (__nv_bfloat162*)Xh, (__nv_bfloat162*)Xl, n);
        n = HQ * DH * DD / 4;
        split_bf16<<<(n + 255) / 256, 256>>>((const float4*)Wq,
            (__nv_bfloat162*)Wqh, (__nv_bfloat162*)Wql, n);
        n = HKV * DH * DD / 4;
        split_bf16<<<(n + 255) / 256, 256>>>((const float4*)Wk,
            (__nv_bfloat162*)Wkh, (__nv_bfloat162*)Wkl, n);
        split_bf16<<<(n + 255) / 256, 256>>>((const float4*)Wv,
            (__nv_bfloat162*)Wvh, (__nv_bfloat162*)Wvl, n);
        n = DD * DD / 4;
        split_bf16<<<(n + 255) / 256, 256>>>((const float4*)Wo,
            (__nv_bfloat162*)Woh, (__nv_bfloat162*)Wol, n);
    }

    // QKV projections (tensor cores, 3-term bf16) -> fp32 head layout
    mma_gemm<true><<<dim3(16, 32), 256, SMEM_DYN>>>(Xh, Xl, Wqh, Wql, Qd, 2048);
    mma_gemm<true><<<dim3(4,  32), 256, SMEM_DYN>>>(Xh, Xl, Wkh, Wkl, Kd, 512);
    mma_gemm<true><<<dim3(4,  32), 256, SMEM_DYN>>>(Xh, Xl, Wvh, Wvl, Vd, 512);

    // RoPE + scale + bf16 hi/lo split for attention operands
    {
        int rowsQ = BB * HQ * SS;
        int rowsK = BB * HKV * SS;
        rope_split<true><<<(rowsQ * 32 + 255) / 256, 256>>>(Qd, Qbh, Qbl, rowsQ, 0.125f);
        rope_split<true><<<(rowsK * 32 + 255) / 256, 256>>>(Kd, Kbh, Kbl, rowsK, 1.0f);
        rope_split<false><<<(rowsK * 32 + 255) / 256, 256>>>(Vd, Vbh, Vbl, rowsK, 1.0f);
    }

    // MMA flash attention (causal)
    flash_mma<<<dim3(SS / 64, HQ, BB), 128, FSMEM>>>(Qbh, Qbl, Kbh, Kbl, Vbh, Vbl, Od);

    // split attention output, output projection
    {
        int n = BB * SS * DD / 4;
        split_bf16<<<(n + 255) / 256, 256>>>((const float4*)Od,
            (__nv_bfloat162*)Oh, (__nv_bfloat162*)Ol, n);
    }
    mma_gemm<false><<<dim3(16, 32), 256, SMEM_DYN>>>(Oh, Ol, Woh, Wol, out, 2048);
}

// round 5
// speedup vs baseline: 3.1560x; 1.0197x over previous
#include <cuda_runtime.h>
#include <cuda_bf16.h>
#include <math.h>
#include <stdint.h>

#define BB   2
#define SS   2048
#define DD   2048
#define HQ   32
#define HKV  8
#define DH   64
#define KDIM 2048

// ---------------------------------------------------------------------------
// Scratch (allocation-free rule: __device__ globals)
// ---------------------------------------------------------------------------
__device__ __nv_bfloat16 g_Xh[(size_t)BB * SS * DD];
__device__ __nv_bfloat16 g_Xl[(size_t)BB * SS * DD];
__device__ __nv_bfloat16 g_Wqh[(size_t)HQ * DH * DD];
__device__ __nv_bfloat16 g_Wql[(size_t)HQ * DH * DD];
__device__ __nv_bfloat16 g_Wkh[(size_t)HKV * DH * DD];
__device__ __nv_bfloat16 g_Wkl[(size_t)HKV * DH * DD];
__device__ __nv_bfloat16 g_Wvh[(size_t)HKV * DH * DD];
__device__ __nv_bfloat16 g_Wvl[(size_t)HKV * DH * DD];
__device__ __nv_bfloat16 g_Woh[(size_t)DD * DD];
__device__ __nv_bfloat16 g_Wol[(size_t)DD * DD];
__device__ __nv_bfloat16 g_Oh[(size_t)BB * SS * DD];
__device__ __nv_bfloat16 g_Ol[(size_t)BB * SS * DD];

// bf16 hi/lo of roped+scaled Q, roped K, V (head layout [b][h][s][d])
__device__ __nv_bfloat16 g_Qbh[(size_t)BB * HQ  * SS * DH];
__device__ __nv_bfloat16 g_Qbl[(size_t)BB * HQ  * SS * DH];
__device__ __nv_bfloat16 g_Kbh[(size_t)BB * HKV * SS * DH];
__device__ __nv_bfloat16 g_Kbl[(size_t)BB * HKV * SS * DH];
__device__ __nv_bfloat16 g_Vbh[(size_t)BB * HKV * SS * DH];
__device__ __nv_bfloat16 g_Vbl[(size_t)BB * HKV * SS * DH];

// ---------------------------------------------------------------------------
// helpers
// ---------------------------------------------------------------------------
__device__ __forceinline__ uint32_t s2u(const void* p) {
    uint32_t r;
    asm("{ .reg .u64 t; cvta.to.shared.u64 t, %1; cvt.u32.u64 %0, t; }"
        : "=r"(r) : "l"(p));
    return r;
}

#define LDM4(r, addr)                                                         \
    asm volatile("ldmatrix.sync.aligned.m8n8.x4.shared.b16 {%0,%1,%2,%3}, [%4];" \
        : "=r"((r)[0]), "=r"((r)[1]), "=r"((r)[2]), "=r"((r)[3]) : "r"(addr))

#define LDM4T(r, addr)                                                        \
    asm volatile("ldmatrix.sync.aligned.m8n8.x4.trans.shared.b16 {%0,%1,%2,%3}, [%4];" \
        : "=r"((r)[0]), "=r"((r)[1]), "=r"((r)[2]), "=r"((r)[3]) : "r"(addr))

#define MMA_BF16(c, a, b0, b1)                                                \
    asm volatile("mma.sync.aligned.m16n8k16.row.col.f32.bf16.bf16.f32 "       \
        "{%0,%1,%2,%3}, {%4,%5,%6,%7}, {%8,%9}, {%0,%1,%2,%3};"               \
        : "+f"((c)[0]), "+f"((c)[1]), "+f"((c)[2]), "+f"((c)[3])              \
        : "r"((a)[0]), "r"((a)[1]), "r"((a)[2]), "r"((a)[3]), "r"(b0), "r"(b1))

#define CP_ASYNC16(dst, src)                                                  \
    asm volatile("cp.async.cg.shared.global [%0], [%1], 16;" :: "r"(dst), "l"(src))

__device__ __forceinline__ uint32_t pack_bf2(float a, float b) {
    __nv_bfloat162 t = __floats2bfloat162_rn(a, b);
    return *reinterpret_cast<uint32_t*>(&t);
}

__device__ __forceinline__ void split2_store(__nv_bfloat16* H, __nv_bfloat16* L,
                                             size_t base, float x1, float x2)
{
    __nv_bfloat16 h1 = __float2bfloat16(x1);
    __nv_bfloat16 h2 = __float2bfloat16(x2);
    __nv_bfloat16 l1 = __float2bfloat16(x1 - __bfloat162float(h1));
    __nv_bfloat16 l2 = __float2bfloat16(x2 - __bfloat162float(h2));
    *reinterpret_cast<__nv_bfloat162*>(H + base) = __nv_bfloat162(h1, h2);
    *reinterpret_cast<__nv_bfloat162*>(L + base) = __nv_bfloat162(l1, l2);
}

// ---------------------------------------------------------------------------
// split fp32 -> bf16 hi/lo (inputs only)
// ---------------------------------------------------------------------------
__global__ void split_bf16(const float4* __restrict__ in,
                           __nv_bfloat162* __restrict__ hi,
                           __nv_bfloat162* __restrict__ lo, int n4)
{
    int i = blockIdx.x * blockDim.x + threadIdx.x;
    if (i >= n4) return;
    float4 a = in[i];
    __nv_bfloat16 h0 = __float2bfloat16(a.x);
    __nv_bfloat16 h1 = __float2bfloat16(a.y);
    __nv_bfloat16 h2 = __float2bfloat16(a.z);
    __nv_bfloat16 h3 = __float2bfloat16(a.w);
    __nv_bfloat16 l0 = __float2bfloat16(a.x - __bfloat162float(h0));
    __nv_bfloat16 l1 = __float2bfloat16(a.y - __bfloat162float(h1));
    __nv_bfloat16 l2 = __float2bfloat16(a.z - __bfloat162float(h2));
    __nv_bfloat16 l3 = __float2bfloat16(a.w - __bfloat162float(h3));
    hi[2 * i + 0] = __nv_bfloat162(h0, h1);
    hi[2 * i + 1] = __nv_bfloat162(h2, h3);
    lo[2 * i + 0] = __nv_bfloat162(l0, l1);
    lo[2 * i + 1] = __nv_bfloat162(l2, l3);
}

// ---------------------------------------------------------------------------
// bf16 3-term mma.sync GEMM: C[M,N] = A[M,K]@B[N,K]^T, K=2048
// CTA 128x128x32, 8 warps, 2-stage cp.async.
// EPI=0: fp32 flat [M][N] -> dstF
// EPI=1: RoPE(scale) + bf16 hi/lo split, head layout [b][h][s][d] -> dstH/dstL
// EPI=2: bf16 hi/lo split, head layout -> dstH/dstL
// ---------------------------------------------------------------------------
#define ROWB   80
#define MATB   10240
#define STAGEB 40960
#define KITERS (KDIM / 32)

template <int EPI>
__global__ __launch_bounds__(256)
void mma_gemm(const __nv_bfloat16* __restrict__ Ah_g,
              const __nv_bfloat16* __restrict__ Al_g,
              const __nv_bfloat16* __restrict__ Bh_g,
              const __nv_bfloat16* __restrict__ Bl_g,
              float* __restrict__ dstF,
              __nv_bfloat16* __restrict__ dstH,
              __nv_bfloat16* __restrict__ dstL,
              int N, float scale)
{
    extern __shared__ __align__(128) char smem[];
    const uint32_t sb = s2u(smem);

    const int tid  = threadIdx.x;
    const int lane = tid & 31;
    const int w    = tid >> 5;
    const int wm   = w & 3;
    const int wn   = w >> 2;
    const int m0   = blockIdx.y * 128;
    const int n0   = blockIdx.x * 128;

    const __nv_bfloat16* srcs[4] = { Ah_g, Al_g, Bh_g, Bl_g };
    const int rowbase[4] = { m0, m0, n0, n0 };

    auto load_stage = [&](int s, int k0) {
#pragma unroll
        for (int i = 0; i < 8; ++i) {
            const int mat = i >> 1;
            const int rem = ((i & 1) << 8) + tid;
            const int row = rem >> 2;
            const int seg = rem & 3;
            uint32_t d = sb + s * STAGEB + mat * MATB + row * ROWB + seg * 16;
            const __nv_bfloat16* p =
                srcs[mat] + (size_t)(rowbase[mat] + row) * KDIM + k0 + seg * 8;
            CP_ASYNC16(d, p);
        }
        asm volatile("cp.async.commit_group;");
    };

    float c[2][8][4];
#pragma unroll
    for (int i = 0; i < 2; ++i)
#pragma unroll
        for (int j = 0; j < 8; ++j)
#pragma unroll
            for (int r = 0; r < 4; ++r) c[i][j][r] = 0.f;

    const uint32_t a_off =
        (uint32_t)((wm * 32 + (lane & 15)) * ROWB + (lane >> 4) * 16);
    const uint32_t b_off =
        (uint32_t)((wn * 64 + (lane >> 4) * 8 + (lane & 7)) * ROWB +
                   ((lane >> 3) & 1) * 16);

    load_stage(0, 0);

    for (int it = 0; it < KITERS; ++it) {
        if (it + 1 < KITERS) {
            load_stage((it + 1) & 1, (it + 1) * 32);
            asm volatile("cp.async.wait_group 1;");
        } else {
            asm volatile("cp.async.wait_group 0;");
        }
        __syncthreads();

        const uint32_t st = sb + (it & 1) * STAGEB;
#pragma unroll
        for (int kk = 0; kk < 2; ++kk) {
            const uint32_t koff = kk * 32;
            uint32_t ah[2][4], al[2][4], bh[4][4], bl[4][4];
#pragma unroll
            for (int i = 0; i < 2; ++i) {
                LDM4(ah[i], st + 0    + a_off + i * (16 * ROWB) + koff);
                LDM4(al[i], st + MATB + a_off + i * (16 * ROWB) + koff);
            }
#pragma unroll
            for (int j2 = 0; j2 < 4; ++j2) {
                LDM4(bh[j2], st + 2 * MATB + b_off + j2 * (16 * ROWB) + koff);
                LDM4(bl[j2], st + 3 * MATB + b_off + j2 * (16 * ROWB) + koff);
            }
#pragma unroll
            for (int i = 0; i < 2; ++i)
#pragma unroll
                for (int j = 0; j < 8; ++j) {
                    const uint32_t* bhp = &bh[j >> 1][(j & 1) * 2];
                    const uint32_t* blp = &bl[j >> 1][(j & 1) * 2];
                    MMA_BF16(c[i][j], ah[i], bhp[0], bhp[1]);
                    MMA_BF16(c[i][j], ah[i], blp[0], blp[1]);
                    MMA_BF16(c[i][j], al[i], bhp[0], bhp[1]);
                }
        }
        __syncthreads();
    }

    const int H = N >> 6;
#pragma unroll
    for (int i = 0; i < 2; ++i) {
        const int r0 = m0 + wm * 32 + i * 16 + (lane >> 2);
#pragma unroll
        for (int j = 0; j < 8; ++j) {
            const int col = n0 + wn * 64 + j * 8 + (lane & 3) * 2;
#pragma unroll
            for (int half = 0; half < 2; ++half) {
                const int row = r0 + half * 8;
                float x1 = c[i][j][half * 2];
                float x2 = c[i][j][half * 2 + 1];
                if (EPI == 0) {
                    *reinterpret_cast<float2*>(dstF + (size_t)row * N + col) =
                        make_float2(x1, x2);
                } else {
                    const int bidx = row >> 11;
                    const int sRow = row & (SS - 1);
                    const int hh = col >> 6, d0 = col & 63;
                    size_t base = ((((size_t)bidx * H + hh) * SS + sRow) << 6) + d0;
                    if (EPI == 1) {
                        float inv = exp2f(-(float)d0 * (13.287712379549449f / 64.0f));
                        float sn, cs;
                        sincosf((float)sRow * inv, &sn, &cs);
                        float y1 = x1 * cs - x2 * sn;
                        float y2 = x1 * sn + x2 * cs;
                        x1 = y1 * scale;
                        x2 = y2 * scale;
                    }
                    split2_store(dstH, dstL, base, x1, x2);
                }
            }
        }
    }
}

// ---------------------------------------------------------------------------
// MMA flash attention (causal, GQA): BM=128 (8 warps x 16 rows), BN=64, Dh=64
// 3-term bf16 for Q.K^T and P.V. grid: (S/128, HQ, B), qb reversed for balance
// smem: Qh/Ql (held) + 2-stage {Kh,Kl,Vh,Vl} ring. Row pitch 144B.
// Output: bf16 hi/lo (flat [b][s][h*64+d]) for the Wo GEMM.
// ---------------------------------------------------------------------------
#define FROW   144
#define QTILE  18432              // 128 * 144
#define FTILE  9216               // 64 * 144
#define FSTAGE 36864              // 4 * FTILE
#define FSMEM  (2 * QTILE + 2 * FSTAGE)   // 110592

__global__ __launch_bounds__(256)
void flash_mma(const __nv_bfloat16* __restrict__ Qh_g,
               const __nv_bfloat16* __restrict__ Ql_g,
               const __nv_bfloat16* __restrict__ Kh_g,
               const __nv_bfloat16* __restrict__ Kl_g,
               const __nv_bfloat16* __restrict__ Vh_g,
               const __nv_bfloat16* __restrict__ Vl_g,
               __nv_bfloat16* __restrict__ OhP,
               __nv_bfloat16* __restrict__ OlP)
{
    extern __shared__ __align__(128) char fsm[];
    const uint32_t sb = s2u(fsm);

    const int tid  = threadIdx.x;
    const int lane = tid & 31;
    const int w    = tid >> 5;
    const int qi   = gridDim.x - 1 - blockIdx.x;   // longest CTAs first
    const int qb   = qi * 128;
    const int h    = blockIdx.y;
    const int b    = blockIdx.z;
    const int kh   = h >> 2;

    const size_t qoff  = (((size_t)b * HQ + h) * SS + qb) * 64;
    const size_t kvrow = ((size_t)b * HKV + kh) * SS;

    // ---- prologue: stage Q (hi/lo), 2 mats x 128 rows x 8 segs ----
#pragma unroll
    for (int i = 0; i < 8; ++i) {
        int idx = tid + 256 * i;
        int mat = idx >> 10;
        int rem = idx & 1023;
        int row = rem >> 3;
        int seg = rem & 7;
        uint32_t d = sb + mat * QTILE + row * FROW + seg * 16;
        const __nv_bfloat16* p = (mat ? Ql_g : Qh_g) + qoff + row * 64 + seg * 8;
        CP_ASYNC16(d, p);
    }
    asm volatile("cp.async.commit_group;");

    auto load_kv = [&](int s, int j0) {
        const __nv_bfloat16* srcs[4] = { Kh_g, Kl_g, Vh_g, Vl_g };
        const size_t off = (kvrow + j0) * 64;
#pragma unroll
        for (int i = 0; i < 8; ++i) {
            int idx = tid + 256 * i;
            int mat = idx >> 9;
            int rem = idx & 511;
            int row = rem >> 3;
            int seg = rem & 7;
            uint32_t d = sb + 2 * QTILE + s * FSTAGE + mat * FTILE + row * FROW + seg * 16;
            CP_ASYNC16(d, srcs[mat] + off + row * 64 + seg * 8);
        }
        asm volatile("cp.async.commit_group;");
    };

    const int nb = qb / 64 + 2;
    load_kv(0, 0);

    float o[8][4];
#pragma unroll
    for (int j = 0; j < 8; ++j)
#pragma unroll
        for (int r = 0; r < 4; ++r) o[j][r] = 0.f;
    float mi[2] = { -1e30f, -1e30f };
    float li[2] = { 0.f, 0.f };

    uint32_t qh[4][4], ql[4][4];

    const uint32_t a_off =
        (uint32_t)((w * 16 + (lane & 15)) * FROW + (lane >> 4) * 16);
    const uint32_t kb_off =
        (uint32_t)(((lane >> 4) * 8 + (lane & 7)) * FROW + ((lane >> 3) & 1) * 16);
    const uint32_t v_off =
        (uint32_t)((lane & 15) * FROW + (lane >> 4) * 16);

    const int row0 = qb + w * 16 + (lane >> 2);

    for (int it = 0; it < nb; ++it) {
        if (it + 1 < nb) {
            load_kv((it + 1) & 1, (it + 1) * 64);
            asm volatile("cp.async.wait_group 1;");
        } else {
            asm volatile("cp.async.wait_group 0;");
        }
        __syncthreads();

        if (it == 0) {
#pragma unroll
            for (int kc = 0; kc < 4; ++kc) {
                LDM4(qh[kc], sb + a_off + kc * 32);
                LDM4(ql[kc], sb + QTILE + a_off + kc * 32);
            }
        }

        const uint32_t kvb = sb + 2 * QTILE + (it & 1) * FSTAGE;
        const int j0 = it * 64;

        // ---- S = Q.K^T (3-term) ----
        float s[8][4];
#pragma unroll
        for (int j = 0; j < 8; ++j)
#pragma unroll
            for (int r = 0; r < 4; ++r) s[j][r] = 0.f;

#pragma unroll
        for (int kc = 0; kc < 4; ++kc) {
            uint32_t bh[4][4], bl[4][4];
#pragma unroll
            for (int j2 = 0; j2 < 4; ++j2) {
                LDM4(bh[j2], kvb + j2 * (16 * FROW) + kb_off + kc * 32);
                LDM4(bl[j2], kvb + FTILE + j2 * (16 * FROW) + kb_off + kc * 32);
            }
#pragma unroll
            for (int j = 0; j < 8; ++j) {
                const uint32_t* bhp = &bh[j >> 1][(j & 1) * 2];
                const uint32_t* blp = &bl[j >> 1][(j & 1) * 2];
                MMA_BF16(s[j], qh[kc], bhp[0], bhp[1]);
                MMA_BF16(s[j], qh[kc], blp[0], blp[1]);
                MMA_BF16(s[j], ql[kc], bhp[0], bhp[1]);
            }
        }

        // ---- causal mask (only blocks that can cross the diagonal) ----
        if (j0 + 63 > qb + w * 16) {
#pragma unroll
            for (int j = 0; j < 8; ++j)
#pragma unroll
                for (int r = 0; r < 4; ++r) {
                    int col = j0 + j * 8 + (lane & 3) * 2 + (r & 1);
                    int row = row0 + (r >> 1) * 8;
                    if (col > row) s[j][r] = -1e30f;
                }
        }

        // ---- online softmax ----
#pragma unroll
        for (int h2 = 0; h2 < 2; ++h2) {
            float mt = -1e30f;
#pragma unroll
            for (int j = 0; j < 8; ++j) {
                mt = fmaxf(mt, s[j][h2 * 2]);
                mt = fmaxf(mt, s[j][h2 * 2 + 1]);
            }
            mt = fmaxf(mt, __shfl_xor_sync(0xffffffffu, mt, 1));
            mt = fmaxf(mt, __shfl_xor_sync(0xffffffffu, mt, 2));
            float mnew  = fmaxf(mi[h2], mt);
            float alpha = __expf(mi[h2] - mnew);
            mi[h2] = mnew;
            float sum = 0.f;
#pragma unroll
            for (int j = 0; j < 8; ++j) {
                float p0 = __expf(s[j][h2 * 2]     - mnew);
                float p1 = __expf(s[j][h2 * 2 + 1] - mnew);
                s[j][h2 * 2]     = p0;
                s[j][h2 * 2 + 1] = p1;
                sum += p0 + p1;
                o[j][h2 * 2]     *= alpha;
                o[j][h2 * 2 + 1] *= alpha;
            }
            sum += __shfl_xor_sync(0xffffffffu, sum, 1);
            sum += __shfl_xor_sync(0xffffffffu, sum, 2);
            li[h2] = li[h2] * alpha + sum;
        }

        // ---- P fragments (hi/lo) ----
        uint32_t ph[4][4], pl[4][4];
#pragma unroll
        for (int kc = 0; kc < 4; ++kc) {
            const int jt = 2 * kc;
            float a0 = s[jt][0],     a1 = s[jt][1];
            float a2 = s[jt][2],     a3 = s[jt][3];
            float b0 = s[jt + 1][0], b1 = s[jt + 1][1];
            float b2 = s[jt + 1][2], b3 = s[jt + 1][3];
            ph[kc][0] = pack_bf2(a0, a1);
            ph[kc][1] = pack_bf2(a2, a3);
            ph[kc][2] = pack_bf2(b0, b1);
            ph[kc][3] = pack_bf2(b2, b3);
            __nv_bfloat162 t;
            t = *reinterpret_cast<__nv_bfloat162*>(&ph[kc][0]);
            pl[kc][0] = pack_bf2(a0 - __bfloat162float(t.x), a1 - __bfloat162float(t.y));
            t = *reinterpret_cast<__nv_bfloat162*>(&ph[kc][1]);
            pl[kc][1] = pack_bf2(a2 - __bfloat162float(t.x), a3 - __bfloat162float(t.y));
            t = *reinterpret_cast<__nv_bfloat162*>(&ph[kc][2]);
            pl[kc][2] = pack_bf2(b0 - __bfloat162float(t.x), b1 - __bfloat162float(t.y));
            t = *reinterpret_cast<__nv_bfloat162*>(&ph[kc][3]);
            pl[kc][3] = pack_bf2(b2 - __bfloat162float(t.x), b3 - __bfloat162float(t.y));
        }

        // ---- O += P.V (3-term), V via ldmatrix.trans ----
#pragma unroll
        for (int kc = 0; kc < 4; ++kc) {
#pragma unroll
            for (int np = 0; np < 4; ++np) {
                uint32_t vh4[4], vl4[4];
                uint32_t va = kvb + 2 * FTILE + kc * (16 * FROW) + v_off + np * 32;
                LDM4T(vh4, va);
                LDM4T(vl4, va + FTILE);
                MMA_BF16(o[2 * np],     ph[kc], vh4[0], vh4[1]);
                MMA_BF16(o[2 * np],     ph[kc], vl4[0], vl4[1]);
                MMA_BF16(o[2 * np],     pl[kc], vh4[0], vh4[1]);
                MMA_BF16(o[2 * np + 1], ph[kc], vh4[2], vh4[3]);
                MMA_BF16(o[2 * np + 1], ph[kc], vl4[2], vl4[3]);
                MMA_BF16(o[2 * np + 1], pl[kc], vh4[2], vh4[3]);
            }
        }

        __syncthreads();
    }

    // ---- finalize: write bf16 hi/lo attention output (flat layout) ----
    float inv0 = 1.0f / li[0];
    float inv1 = 1.0f / li[1];
#pragma unroll
    for (int j = 0; j < 8; ++j) {
        const int col = j * 8 + (lane & 3) * 2;
        size_t base0 = ((size_t)(b * SS + row0)) * DD + h * 64 + col;
        size_t base1 = ((size_t)(b * SS + row0 + 8)) * DD + h * 64 + col;
        split2_store(OhP, OlP, base0, o[j][0] * inv0, o[j][1] * inv0);
        split2_store(OhP, OlP, base1, o[j][2] * inv1, o[j][3] * inv1);
    }
}

// ---------------------------------------------------------------------------
// Host
// ---------------------------------------------------------------------------
extern "C" void kernel_launch(void* const* d_in, const int* in_sizes, int n_in,
                              void* d_out, int out_size)
{
    const float* x  = (const float*)d_in[0];
    const float* Wq = (const float*)d_in[1];
    const float* Wk = (const float*)d_in[2];
    const float* Wv = (const float*)d_in[3];
    const float* Wo = (const float*)d_in[4];
    float* out = (float*)d_out;

    __nv_bfloat16 *Xh, *Xl, *Wqh, *Wql, *Wkh, *Wkl, *Wvh, *Wvl, *Woh, *Wol, *Oh, *Ol;
    __nv_bfloat16 *Qbh, *Qbl, *Kbh, *Kbl, *Vbh, *Vbl;
    cudaGetSymbolAddress((void**)&Xh, g_Xh);
    cudaGetSymbolAddress((void**)&Xl, g_Xl);
    cudaGetSymbolAddress((void**)&Wqh, g_Wqh);
    cudaGetSymbolAddress((void**)&Wql, g_Wql);
    cudaGetSymbolAddress((void**)&Wkh, g_Wkh);
    cudaGetSymbolAddress((void**)&Wkl, g_Wkl);
    cudaGetSymbolAddress((void**)&Wvh, g_Wvh);
    cudaGetSymbolAddress((void**)&Wvl, g_Wvl);
    cudaGetSymbolAddress((void**)&Woh, g_Woh);
    cudaGetSymbolAddress((void**)&Wol, g_Wol);
    cudaGetSymbolAddress((void**)&Oh, g_Oh);
    cudaGetSymbolAddress((void**)&Ol, g_Ol);
    cudaGetSymbolAddress((void**)&Qbh, g_Qbh);
    cudaGetSymbolAddress((void**)&Qbl, g_Qbl);
    cudaGetSymbolAddress((void**)&Kbh, g_Kbh);
    cudaGetSymbolAddress((void**)&Kbl, g_Kbl);
    cudaGetSymbolAddress((void**)&Vbh, g_Vbh);
    cudaGetSymbolAddress((void**)&Vbl, g_Vbl);

    const int SMEM_DYN = 2 * STAGEB;
    cudaFuncSetAttribute(mma_gemm<0>, cudaFuncAttributeMaxDynamicSharedMemorySize, SMEM_DYN);
    cudaFuncSetAttribute(mma_gemm<1>, cudaFuncAttributeMaxDynamicSharedMemorySize, SMEM_DYN);
    cudaFuncSetAttribute(mma_gemm<2>, cudaFuncAttributeMaxDynamicSharedMemorySize, SMEM_DYN);
    cudaFuncSetAttribute(flash_mma, cudaFuncAttributeMaxDynamicSharedMemorySize, FSMEM);

    // splits of the fp32 inputs
    {
        int n;
        n = BB * SS * DD / 4;
        split_bf16<<<(n + 255) / 256, 256>>>((const float4*)x,
            (__nv_bfloat162*)Xh, (__nv_bfloat162*)Xl, n);
        n = HQ * DH * DD / 4;
        split_bf16<<<(n + 255) / 256, 256>>>((const float4*)Wq,
            (__nv_bfloat162*)Wqh, (__nv_bfloat162*)Wql, n);
        n = HKV * DH * DD / 4;
        split_bf16<<<(n + 255) / 256, 256>>>((const float4*)Wk,
            (__nv_bfloat162*)Wkh, (__nv_bfloat162*)Wkl, n);
        split_bf16<<<(n + 255) / 256, 256>>>((const float4*)Wv,
            (__nv_bfloat162*)Wvh, (__nv_bfloat162*)Wvl, n);
        n = DD * DD / 4;
        split_bf16<<<(n + 255) / 256, 256>>>((const float4*)Wo,
            (__nv_bfloat162*)Woh, (__nv_bfloat162*)Wol, n);
    }

    // QKV projections with fused RoPE/scale/split epilogues
    mma_gemm<1><<<dim3(16, 32), 256, SMEM_DYN>>>(Xh, Xl, Wqh, Wql,
        nullptr, Qbh, Qbl, 2048, 0.125f);
    mma_gemm<1><<<dim3(4, 32), 256, SMEM_DYN>>>(Xh, Xl, Wkh, Wkl,
        nullptr, Kbh, Kbl, 512, 1.0f);
    mma_gemm<2><<<dim3(4, 32), 256, SMEM_DYN>>>(Xh, Xl, Wvh, Wvl,
        nullptr, Vbh, Vbl, 512, 1.0f);

    // MMA flash attention (causal), outputs bf16 hi/lo
    flash_mma<<<dim3(SS / 128, HQ, BB), 256, FSMEM>>>(Qbh, Qbl, Kbh, Kbl, Vbh, Vbl, Oh, Ol);

    // output projection -> fp32 result
    mma_gemm<0><<<dim3(16, 32), 256, SMEM_DYN>>>(Oh, Ol, Woh, Wol,
        out, nullptr, nullptr, 2048, 1.0f);
}

// round 6
// speedup vs baseline: 3.3150x; 1.0504x over previous
#include <cuda_runtime.h>
#include <cuda_bf16.h>
#include <math.h>
#include <stdint.h>

#define BB   2
#define SS   2048
#define DD   2048
#define HQ   32
#define HKV  8
#define DH   64
#define KDIM 2048

// ---------------------------------------------------------------------------
// Scratch (allocation-free rule: __device__ globals)
// ---------------------------------------------------------------------------
__device__ __nv_bfloat16 g_Xh[(size_t)BB * SS * DD];
__device__ __nv_bfloat16 g_Xl[(size_t)BB * SS * DD];
__device__ __nv_bfloat16 g_Wqh[(size_t)HQ * DH * DD];
__device__ __nv_bfloat16 g_Wql[(size_t)HQ * DH * DD];
__device__ __nv_bfloat16 g_Wkh[(size_t)HKV * DH * DD];
__device__ __nv_bfloat16 g_Wkl[(size_t)HKV * DH * DD];
__device__ __nv_bfloat16 g_Wvh[(size_t)HKV * DH * DD];
__device__ __nv_bfloat16 g_Wvl[(size_t)HKV * DH * DD];
__device__ __nv_bfloat16 g_Woh[(size_t)DD * DD];
__device__ __nv_bfloat16 g_Wol[(size_t)DD * DD];
__device__ __nv_bfloat16 g_Oh[(size_t)BB * SS * DD];
__device__ __nv_bfloat16 g_Ol[(size_t)BB * SS * DD];

// bf16 hi/lo of roped+scaled Q, roped K, V (head layout [b][h][s][d])
__device__ __nv_bfloat16 g_Qbh[(size_t)BB * HQ  * SS * DH];
__device__ __nv_bfloat16 g_Qbl[(size_t)BB * HQ  * SS * DH];
__device__ __nv_bfloat16 g_Kbh[(size_t)BB * HKV * SS * DH];
__device__ __nv_bfloat16 g_Kbl[(size_t)BB * HKV * SS * DH];
__device__ __nv_bfloat16 g_Vbh[(size_t)BB * HKV * SS * DH];
__device__ __nv_bfloat16 g_Vbl[(size_t)BB * HKV * SS * DH];

// ---------------------------------------------------------------------------
// helpers
// ---------------------------------------------------------------------------
__device__ __forceinline__ uint32_t s2u(const void* p) {
    uint32_t r;
    asm("{ .reg .u64 t; cvta.to.shared.u64 t, %1; cvt.u32.u64 %0, t; }"
        : "=r"(r) : "l"(p));
    return r;
}

#define LDM4(r, addr)                                                         \
    asm volatile("ldmatrix.sync.aligned.m8n8.x4.shared.b16 {%0,%1,%2,%3}, [%4];" \
        : "=r"((r)[0]), "=r"((r)[1]), "=r"((r)[2]), "=r"((r)[3]) : "r"(addr))

#define LDM4T(r, addr)                                                        \
    asm volatile("ldmatrix.sync.aligned.m8n8.x4.trans.shared.b16 {%0,%1,%2,%3}, [%4];" \
        : "=r"((r)[0]), "=r"((r)[1]), "=r"((r)[2]), "=r"((r)[3]) : "r"(addr))

#define MMA_BF16(c, a, b0, b1)                                                \
    asm volatile("mma.sync.aligned.m16n8k16.row.col.f32.bf16.bf16.f32 "       \
        "{%0,%1,%2,%3}, {%4,%5,%6,%7}, {%8,%9}, {%0,%1,%2,%3};"               \
        : "+f"((c)[0]), "+f"((c)[1]), "+f"((c)[2]), "+f"((c)[3])              \
        : "r"((a)[0]), "r"((a)[1]), "r"((a)[2]), "r"((a)[3]), "r"(b0), "r"(b1))

#define CP_ASYNC16(dst, src)                                                  \
    asm volatile("cp.async.cg.shared.global [%0], [%1], 16;" :: "r"(dst), "l"(src))

__device__ __forceinline__ uint32_t pack_bf2(float a, float b) {
    __nv_bfloat162 t = __floats2bfloat162_rn(a, b);
    return *reinterpret_cast<uint32_t*>(&t);
}

__device__ __forceinline__ void split2_store(__nv_bfloat16* H, __nv_bfloat16* L,
                                             size_t base, float x1, float x2)
{
    __nv_bfloat16 h1 = __float2bfloat16(x1);
    __nv_bfloat16 h2 = __float2bfloat16(x2);
    __nv_bfloat16 l1 = __float2bfloat16(x1 - __bfloat162float(h1));
    __nv_bfloat16 l2 = __float2bfloat16(x2 - __bfloat162float(h2));
    *reinterpret_cast<__nv_bfloat162*>(H + base) = __nv_bfloat162(h1, h2);
    *reinterpret_cast<__nv_bfloat162*>(L + base) = __nv_bfloat162(l1, l2);
}

// ---------------------------------------------------------------------------
// split fp32 -> bf16 hi/lo (inputs only)
// ---------------------------------------------------------------------------
__global__ void split_bf16(const float4* __restrict__ in,
                           __nv_bfloat162* __restrict__ hi,
                           __nv_bfloat162* __restrict__ lo, int n4)
{
    int i = blockIdx.x * blockDim.x + threadIdx.x;
    if (i >= n4) return;
    float4 a = in[i];
    __nv_bfloat16 h0 = __float2bfloat16(a.x);
    __nv_bfloat16 h1 = __float2bfloat16(a.y);
    __nv_bfloat16 h2 = __float2bfloat16(a.z);
    __nv_bfloat16 h3 = __float2bfloat16(a.w);
    __nv_bfloat16 l0 = __float2bfloat16(a.x - __bfloat162float(h0));
    __nv_bfloat16 l1 = __float2bfloat16(a.y - __bfloat162float(h1));
    __nv_bfloat16 l2 = __float2bfloat16(a.z - __bfloat162float(h2));
    __nv_bfloat16 l3 = __float2bfloat16(a.w - __bfloat162float(h3));
    hi[2 * i + 0] = __nv_bfloat162(h0, h1);
    hi[2 * i + 1] = __nv_bfloat162(h2, h3);
    lo[2 * i + 0] = __nv_bfloat162(l0, l1);
    lo[2 * i + 1] = __nv_bfloat162(l2, l3);
}

// ---------------------------------------------------------------------------
// core 3-term bf16 MMA loop shared by both GEMMs (CTA 128x128x2048)
// ---------------------------------------------------------------------------
#define ROWB   80
#define MATB   10240
#define STAGEB 40960
#define KITERS (KDIM / 32)

struct GemmCore {
    float c[2][8][4];
    uint32_t a_off, b_off;
};

__device__ __forceinline__ void gemm_mainloop(
    uint32_t sb, int tid, int lane, int wm, int wn,
    const __nv_bfloat16* Ah_g, const __nv_bfloat16* Al_g,
    const __nv_bfloat16* Bh_g, const __nv_bfloat16* Bl_g,
    int m0, int n0, GemmCore& g)
{
#pragma unroll
    for (int i = 0; i < 2; ++i)
#pragma unroll
        for (int j = 0; j < 8; ++j)
#pragma unroll
            for (int r = 0; r < 4; ++r) g.c[i][j][r] = 0.f;

    g.a_off = (uint32_t)((wm * 32 + (lane & 15)) * ROWB + (lane >> 4) * 16);
    g.b_off = (uint32_t)((wn * 64 + (lane >> 4) * 8 + (lane & 7)) * ROWB +
                         ((lane >> 3) & 1) * 16);

    const __nv_bfloat16* srcs[4] = { Ah_g, Al_g, Bh_g, Bl_g };
    const int rowbase[4] = { m0, m0, n0, n0 };

    auto load_stage = [&](int s, int k0) {
#pragma unroll
        for (int i = 0; i < 8; ++i) {
            const int mat = i >> 1;
            const int rem = ((i & 1) << 8) + tid;
            const int row = rem >> 2;
            const int seg = rem & 3;
            uint32_t d = sb + s * STAGEB + mat * MATB + row * ROWB + seg * 16;
            const __nv_bfloat16* p =
                srcs[mat] + (size_t)(rowbase[mat] + row) * KDIM + k0 + seg * 8;
            CP_ASYNC16(d, p);
        }
        asm volatile("cp.async.commit_group;");
    };

    load_stage(0, 0);

    for (int it = 0; it < KITERS; ++it) {
        if (it + 1 < KITERS) {
            load_stage((it + 1) & 1, (it + 1) * 32);
            asm volatile("cp.async.wait_group 1;");
        } else {
            asm volatile("cp.async.wait_group 0;");
        }
        __syncthreads();

        const uint32_t st = sb + (it & 1) * STAGEB;
#pragma unroll
        for (int kk = 0; kk < 2; ++kk) {
            const uint32_t koff = kk * 32;
            uint32_t ah[2][4], al[2][4], bh[4][4], bl[4][4];
#pragma unroll
            for (int i = 0; i < 2; ++i) {
                LDM4(ah[i], st + 0    + g.a_off + i * (16 * ROWB) + koff);
                LDM4(al[i], st + MATB + g.a_off + i * (16 * ROWB) + koff);
            }
#pragma unroll
            for (int j2 = 0; j2 < 4; ++j2) {
                LDM4(bh[j2], st + 2 * MATB + g.b_off + j2 * (16 * ROWB) + koff);
                LDM4(bl[j2], st + 3 * MATB + g.b_off + j2 * (16 * ROWB) + koff);
            }
#pragma unroll
            for (int i = 0; i < 2; ++i)
#pragma unroll
                for (int j = 0; j < 8; ++j) {
                    const uint32_t* bhp = &bh[j >> 1][(j & 1) * 2];
                    const uint32_t* blp = &bl[j >> 1][(j & 1) * 2];
                    MMA_BF16(g.c[i][j], ah[i], bhp[0], bhp[1]);
                    MMA_BF16(g.c[i][j], ah[i], blp[0], blp[1]);
                    MMA_BF16(g.c[i][j], al[i], bhp[0], bhp[1]);
                }
        }
        __syncthreads();
    }
}

// ---------------------------------------------------------------------------
// merged QKV projection: one launch, grid (24, 32).
// bx 0..15 -> Q (rope, scale 1/8), 16..19 -> K (rope), 20..23 -> V (plain)
// epilogue: bf16 hi/lo split to head layout [b][h][s][d]
// ---------------------------------------------------------------------------
__global__ __launch_bounds__(256)
void qkv_gemm(const __nv_bfloat16* __restrict__ Xh_g,
              const __nv_bfloat16* __restrict__ Xl_g,
              const __nv_bfloat16* __restrict__ Wqh_g, const __nv_bfloat16* __restrict__ Wql_g,
              const __nv_bfloat16* __restrict__ Wkh_g, const __nv_bfloat16* __restrict__ Wkl_g,
              const __nv_bfloat16* __restrict__ Wvh_g, const __nv_bfloat16* __restrict__ Wvl_g,
              __nv_bfloat16* __restrict__ Qh, __nv_bfloat16* __restrict__ Ql,
              __nv_bfloat16* __restrict__ Kh, __nv_bfloat16* __restrict__ Kl,
              __nv_bfloat16* __restrict__ Vh, __nv_bfloat16* __restrict__ Vl)
{
    extern __shared__ __align__(128) char smem[];
    const uint32_t sb = s2u(smem);

    const int tid  = threadIdx.x;
    const int lane = tid & 31;
    const int w    = tid >> 5;
    const int wm   = w & 3;
    const int wn   = w >> 2;
    const int bx   = blockIdx.x;
    const int m0   = blockIdx.y * 128;

    const __nv_bfloat16 *Bh_g, *Bl_g;
    __nv_bfloat16 *dH, *dL;
    int n0, Hn;
    bool rope;
    float scale;
    if (bx < 16) {
        Bh_g = Wqh_g; Bl_g = Wql_g; dH = Qh; dL = Ql;
        n0 = bx * 128; Hn = HQ; rope = true; scale = 0.125f;
    } else if (bx < 20) {
        Bh_g = Wkh_g; Bl_g = Wkl_g; dH = Kh; dL = Kl;
        n0 = (bx - 16) * 128; Hn = HKV; rope = true; scale = 1.0f;
    } else {
        Bh_g = Wvh_g; Bl_g = Wvl_g; dH = Vh; dL = Vl;
        n0 = (bx - 20) * 128; Hn = HKV; rope = false; scale = 1.0f;
    }

    GemmCore g;
    gemm_mainloop(sb, tid, lane, wm, wn, Xh_g, Xl_g, Bh_g, Bl_g, m0, n0, g);

#pragma unroll
    for (int i = 0; i < 2; ++i) {
        const int r0 = m0 + wm * 32 + i * 16 + (lane >> 2);
#pragma unroll
        for (int j = 0; j < 8; ++j) {
            const int col = n0 + wn * 64 + j * 8 + (lane & 3) * 2;
#pragma unroll
            for (int half = 0; half < 2; ++half) {
                const int row = r0 + half * 8;
                float x1 = g.c[i][j][half * 2];
                float x2 = g.c[i][j][half * 2 + 1];
                const int bidx = row >> 11;
                const int sRow = row & (SS - 1);
                const int hh = col >> 6, d0 = col & 63;
                size_t base = ((((size_t)bidx * Hn + hh) * SS + sRow) << 6) + d0;
                if (rope) {
                    float inv = exp2f(-(float)d0 * (13.287712379549449f / 64.0f));
                    float sn, cs;
                    sincosf((float)sRow * inv, &sn, &cs);
                    float y1 = x1 * cs - x2 * sn;
                    float y2 = x1 * sn + x2 * cs;
                    x1 = y1 * scale;
                    x2 = y2 * scale;
                }
                split2_store(dH, dL, base, x1, x2);
            }
        }
    }
}

// ---------------------------------------------------------------------------
// output projection: fp32 flat result
// ---------------------------------------------------------------------------
__global__ __launch_bounds__(256)
void wo_gemm(const __nv_bfloat16* __restrict__ Ah_g,
             const __nv_bfloat16* __restrict__ Al_g,
             const __nv_bfloat16* __restrict__ Bh_g,
             const __nv_bfloat16* __restrict__ Bl_g,
             float* __restrict__ dst)
{
    extern __shared__ __align__(128) char smem[];
    const uint32_t sb = s2u(smem);

    const int tid  = threadIdx.x;
    const int lane = tid & 31;
    const int w    = tid >> 5;
    const int wm   = w & 3;
    const int wn   = w >> 2;
    const int m0   = blockIdx.y * 128;
    const int n0   = blockIdx.x * 128;

    GemmCore g;
    gemm_mainloop(sb, tid, lane, wm, wn, Ah_g, Al_g, Bh_g, Bl_g, m0, n0, g);

#pragma unroll
    for (int i = 0; i < 2; ++i) {
        const int r0 = m0 + wm * 32 + i * 16 + (lane >> 2);
#pragma unroll
        for (int j = 0; j < 8; ++j) {
            const int col = n0 + wn * 64 + j * 8 + (lane & 3) * 2;
#pragma unroll
            for (int half = 0; half < 2; ++half) {
                const int row = r0 + half * 8;
                *reinterpret_cast<float2*>(dst + (size_t)row * DD + col) =
                    make_float2(g.c[i][j][half * 2], g.c[i][j][half * 2 + 1]);
            }
        }
    }
}

// ---------------------------------------------------------------------------
// MMA flash attention (causal, GQA): BM=128 (8 warps x 16 rows), BN=128, Dh=64
// 3-term bf16 for both GEMMs. grid: (S/128, HQ, B), qb reversed for balance.
// smem: Qh/Ql (held) + 2-stage {Kh,Kl,Vh,Vl} ring of 128-row tiles.
// ---------------------------------------------------------------------------
#define FROW   144
#define QTILE  18432               // 128 * 144
#define KTILE  18432               // 128 * 144 per matrix
#define KVSTG  73728               // 4 * KTILE
#define FSMEM  (2 * QTILE + 2 * KVSTG)   // 184320

__global__ __launch_bounds__(256)
void flash_mma(const __nv_bfloat16* __restrict__ Qh_g,
               const __nv_bfloat16* __restrict__ Ql_g,
               const __nv_bfloat16* __restrict__ Kh_g,
               const __nv_bfloat16* __restrict__ Kl_g,
               const __nv_bfloat16* __restrict__ Vh_g,
               const __nv_bfloat16* __restrict__ Vl_g,
               __nv_bfloat16* __restrict__ OhP,
               __nv_bfloat16* __restrict__ OlP)
{
    extern __shared__ __align__(128) char fsm[];
    const uint32_t sb = s2u(fsm);

    const int tid  = threadIdx.x;
    const int lane = tid & 31;
    const int w    = tid >> 5;
    const int qi   = gridDim.x - 1 - blockIdx.x;   // longest CTAs first
    const int qb   = qi * 128;
    const int h    = blockIdx.y;
    const int b    = blockIdx.z;
    const int kh   = h >> 2;

    const size_t qoff  = (((size_t)b * HQ + h) * SS + qb) * 64;
    const size_t kvrow = ((size_t)b * HKV + kh) * SS;

    // ---- prologue: stage Q (hi/lo) ----
#pragma unroll
    for (int i = 0; i < 8; ++i) {
        int idx = tid + 256 * i;
        int mat = idx >> 10;
        int rem = idx & 1023;
        int row = rem >> 3;
        int seg = rem & 7;
        uint32_t d = sb + mat * QTILE + row * FROW + seg * 16;
        const __nv_bfloat16* p = (mat ? Ql_g : Qh_g) + qoff + row * 64 + seg * 8;
        CP_ASYNC16(d, p);
    }
    asm volatile("cp.async.commit_group;");

    auto load_kv = [&](int s, int j0) {
        const __nv_bfloat16* srcs[4] = { Kh_g, Kl_g, Vh_g, Vl_g };
        const size_t off = (kvrow + j0) * 64;
#pragma unroll
        for (int i = 0; i < 16; ++i) {
            int idx = tid + 256 * i;
            int mat = idx >> 10;
            int rem = idx & 1023;
            int row = rem >> 3;
            int seg = rem & 7;
            uint32_t d = sb + 2 * QTILE + s * KVSTG + mat * KTILE + row * FROW + seg * 16;
            CP_ASYNC16(d, srcs[mat] + off + row * 64 + seg * 8);
        }
        asm volatile("cp.async.commit_group;");
    };

    const int nb = qb / 128 + 1;
    load_kv(0, 0);

    float o[8][4];
#pragma unroll
    for (int j = 0; j < 8; ++j)
#pragma unroll
        for (int r = 0; r < 4; ++r) o[j][r] = 0.f;
    float mi[2] = { -1e30f, -1e30f };
    float li[2] = { 0.f, 0.f };

    uint32_t qh[4][4], ql[4][4];

    const uint32_t a_off =
        (uint32_t)((w * 16 + (lane & 15)) * FROW + (lane >> 4) * 16);
    const uint32_t kb_off =
        (uint32_t)(((lane >> 4) * 8 + (lane & 7)) * FROW + ((lane >> 3) & 1) * 16);
    const uint32_t v_off =
        (uint32_t)((lane & 15) * FROW + (lane >> 4) * 16);

    const int row0 = qb + w * 16 + (lane >> 2);

    for (int it = 0; it < nb; ++it) {
        if (it + 1 < nb) {
            load_kv((it + 1) & 1, (it + 1) * 128);
            asm volatile("cp.async.wait_group 1;");
        } else {
            asm volatile("cp.async.wait_group 0;");
        }
        __syncthreads();

        if (it == 0) {
#pragma unroll
            for (int kc = 0; kc < 4; ++kc) {
                LDM4(qh[kc], sb + a_off + kc * 32);
                LDM4(ql[kc], sb + QTILE + a_off + kc * 32);
            }
        }

        const uint32_t kvb = sb + 2 * QTILE + (it & 1) * KVSTG;
        const int j0 = it * 128;

        // ---- S = Q.K^T (3-term), 16 j-tiles processed in two 64-col halves --
        float s[16][4];
#pragma unroll
        for (int j = 0; j < 16; ++j)
#pragma unroll
            for (int r = 0; r < 4; ++r) s[j][r] = 0.f;

#pragma unroll
        for (int jh = 0; jh < 2; ++jh) {
#pragma unroll
            for (int kc = 0; kc < 4; ++kc) {
                uint32_t bh[4][4], bl[4][4];
#pragma unroll
                for (int j2 = 0; j2 < 4; ++j2) {
                    uint32_t ba = kvb + (jh * 4 + j2) * (16 * FROW) + kb_off + kc * 32;
                    LDM4(bh[j2], ba);
                    LDM4(bl[j2], ba + KTILE);
                }
#pragma unroll
                for (int j = 0; j < 8; ++j) {
                    float* cs = s[jh * 8 + j];
                    const uint32_t* bhp = &bh[j >> 1][(j & 1) * 2];
                    const uint32_t* blp = &bl[j >> 1][(j & 1) * 2];
                    MMA_BF16(cs, qh[kc], bhp[0], bhp[1]);
                    MMA_BF16(cs, qh[kc], blp[0], blp[1]);
                    MMA_BF16(cs, ql[kc], bhp[0], bhp[1]);
                }
            }
        }

        // ---- causal mask (diagonal block = last iteration) ----
        if (j0 == qb) {
#pragma unroll
            for (int j = 0; j < 16; ++j)
#pragma unroll
                for (int r = 0; r < 4; ++r) {
                    int col = j0 + j * 8 + (lane & 3) * 2 + (r & 1);
                    int row = row0 + (r >> 1) * 8;
                    if (col > row) s[j][r] = -1e30f;
                }
        }

        // ---- online softmax ----
#pragma unroll
        for (int h2 = 0; h2 < 2; ++h2) {
            float mt = -1e30f;
#pragma unroll
            for (int j = 0; j < 16; ++j) {
                mt = fmaxf(mt, s[j][h2 * 2]);
                mt = fmaxf(mt, s[j][h2 * 2 + 1]);
            }
            mt = fmaxf(mt, __shfl_xor_sync(0xffffffffu, mt, 1));
            mt = fmaxf(mt, __shfl_xor_sync(0xffffffffu, mt, 2));
            float mnew  = fmaxf(mi[h2], mt);
            float alpha = __expf(mi[h2] - mnew);
            mi[h2] = mnew;
            float sum = 0.f;
#pragma unroll
            for (int j = 0; j < 16; ++j) {
                float p0 = __expf(s[j][h2 * 2]     - mnew);
                float p1 = __expf(s[j][h2 * 2 + 1] - mnew);
                s[j][h2 * 2]     = p0;
                s[j][h2 * 2 + 1] = p1;
                sum += p0 + p1;
                o[j & 7][h2 * 2]     *= (j == 0) ? alpha : 1.f;
                o[j & 7][h2 * 2 + 1] *= (j == 0) ? alpha : 1.f;
            }
            // apply alpha to remaining o entries (j=1..7 handled above only for j==0)
#pragma unroll
            for (int j = 1; j < 8; ++j) {
                o[j][h2 * 2]     *= alpha;
                o[j][h2 * 2 + 1] *= alpha;
            }
            sum += __shfl_xor_sync(0xffffffffu, sum, 1);
            sum += __shfl_xor_sync(0xffffffffu, sum, 2);
            li[h2] = li[h2] * alpha + sum;
        }

        // ---- P fragments (hi/lo), 8 k-chunks of 16 ----
        uint32_t ph[8][4], pl[8][4];
#pragma unroll
        for (int kc = 0; kc < 8; ++kc) {
            const int jt = 2 * kc;
            float a0 = s[jt][0],     a1 = s[jt][1];
            float a2 = s[jt][2],     a3 = s[jt][3];
            float b0 = s[jt + 1][0], b1 = s[jt + 1][1];
            float b2 = s[jt + 1][2], b3 = s[jt + 1][3];
            ph[kc][0] = pack_bf2(a0, a1);
            ph[kc][1] = pack_bf2(a2, a3);
            ph[kc][2] = pack_bf2(b0, b1);
            ph[kc][3] = pack_bf2(b2, b3);
            __nv_bfloat162 t;
            t = *reinterpret_cast<__nv_bfloat162*>(&ph[kc][0]);
            pl[kc][0] = pack_bf2(a0 - __bfloat162float(t.x), a1 - __bfloat162float(t.y));
            t = *reinterpret_cast<__nv_bfloat162*>(&ph[kc][1]);
            pl[kc][1] = pack_bf2(a2 - __bfloat162float(t.x), a3 - __bfloat162float(t.y));
            t = *reinterpret_cast<__nv_bfloat162*>(&ph[kc][2]);
            pl[kc][2] = pack_bf2(b0 - __bfloat162float(t.x), b1 - __bfloat162float(t.y));
            t = *reinterpret_cast<__nv_bfloat162*>(&ph[kc][3]);
            pl[kc][3] = pack_bf2(b2 - __bfloat162float(t.x), b3 - __bfloat162float(t.y));
        }

        // ---- O += P.V (3-term) ----
        const uint32_t vbase = kvb + 2 * KTILE;
#pragma unroll
        for (int kc = 0; kc < 8; ++kc) {
#pragma unroll
            for (int np = 0; np < 4; ++np) {
                uint32_t vh4[4], vl4[4];
                uint32_t va = vbase + kc * (16 * FROW) + v_off + np * 32;
                LDM4T(vh4, va);
                LDM4T(vl4, va + KTILE);
                MMA_BF16(o[2 * np],     ph[kc], vh4[0], vh4[1]);
                MMA_BF16(o[2 * np],     ph[kc], vl4[0], vl4[1]);
                MMA_BF16(o[2 * np],     pl[kc], vh4[0], vh4[1]);
                MMA_BF16(o[2 * np + 1], ph[kc], vh4[2], vh4[3]);
                MMA_BF16(o[2 * np + 1], ph[kc], vl4[2], vl4[3]);
                MMA_BF16(o[2 * np + 1], pl[kc], vh4[2], vh4[3]);
            }
        }

        __syncthreads();
    }

    // ---- finalize: bf16 hi/lo attention output (flat [b][s][h*64+d]) ----
    float inv0 = 1.0f / li[0];
    float inv1 = 1.0f / li[1];
#pragma unroll
    for (int j = 0; j < 8; ++j) {
        const int col = j * 8 + (lane & 3) * 2;
        size_t base0 = ((size_t)(b * SS + row0)) * DD + h * 64 + col;
        size_t base1 = ((size_t)(b * SS + row0 + 8)) * DD + h * 64 + col;
        split2_store(OhP, OlP, base0, o[j][0] * inv0, o[j][1] * inv0);
        split2_store(OhP, OlP, base1, o[j][2] * inv1, o[j][3] * inv1);
    }
}

// ---------------------------------------------------------------------------
// Host
// ---------------------------------------------------------------------------
extern "C" void kernel_launch(void* const* d_in, const int* in_sizes, int n_in,
                              void* d_out, int out_size)
{
    const float* x  = (const float*)d_in[0];
    const float* Wq = (const float*)d_in[1];
    const float* Wk = (const float*)d_in[2];
    const float* Wv = (const float*)d_in[3];
    const float* Wo = (const float*)d_in[4];
    float* out = (float*)d_out;

    __nv_bfloat16 *Xh, *Xl, *Wqh, *Wql, *Wkh, *Wkl, *Wvh, *Wvl, *Woh, *Wol, *Oh, *Ol;
    __nv_bfloat16 *Qbh, *Qbl, *Kbh, *Kbl, *Vbh, *Vbl;
    cudaGetSymbolAddress((void**)&Xh, g_Xh);
    cudaGetSymbolAddress((void**)&Xl, g_Xl);
    cudaGetSymbolAddress((void**)&Wqh, g_Wqh);
    cudaGetSymbolAddress((void**)&Wql, g_Wql);
    cudaGetSymbolAddress((void**)&Wkh, g_Wkh);
    cudaGetSymbolAddress((void**)&Wkl, g_Wkl);
    cudaGetSymbolAddress((void**)&Wvh, g_Wvh);
    cudaGetSymbolAddress((void**)&Wvl, g_Wvl);
    cudaGetSymbolAddress((void**)&Woh, g_Woh);
    cudaGetSymbolAddress((void**)&Wol, g_Wol);
    cudaGetSymbolAddress((void**)&Oh, g_Oh);
    cudaGetSymbolAddress((void**)&Ol, g_Ol);
    cudaGetSymbolAddress((void**)&Qbh, g_Qbh);
    cudaGetSymbolAddress((void**)&Qbl, g_Qbl);
    cudaGetSymbolAddress((void**)&Kbh, g_Kbh);
    cudaGetSymbolAddress((void**)&Kbl, g_Kbl);
    cudaGetSymbolAddress((void**)&Vbh, g_Vbh);
    cudaGetSymbolAddress((void**)&Vbl, g_Vbl);

    const int SMEM_DYN = 2 * STAGEB;
    cudaFuncSetAttribute(qkv_gemm, cudaFuncAttributeMaxDynamicSharedMemorySize, SMEM_DYN);
    cudaFuncSetAttribute(wo_gemm,  cudaFuncAttributeMaxDynamicSharedMemorySize, SMEM_DYN);
    cudaFuncSetAttribute(flash_mma, cudaFuncAttributeMaxDynamicSharedMemorySize, FSMEM);

    // splits of the fp32 inputs
    {
        int n;
        n = BB * SS * DD / 4;
        split_bf16<<<(n + 255) / 256, 256>>>((const float4*)x,
            (__nv_bfloat162*)Xh, (__nv_bfloat162*)Xl, n);
        n = HQ * DH * DD / 4;
        split_bf16<<<(n + 255) / 256, 256>>>((const float4*)Wq,
            (__nv_bfloat162*)Wqh, (__nv_bfloat162*)Wql, n);
        n = HKV * DH * DD / 4;
        split_bf16<<<(n + 255) / 256, 256>>>((const float4*)Wk,
            (__nv_bfloat162*)Wkh, (__nv_bfloat162*)Wkl, n);
        split_bf16<<<(n + 255) / 256, 256>>>((const float4*)Wv,
            (__nv_bfloat162*)Wvh, (__nv_bfloat162*)Wvl, n);
        n = DD * DD / 4;
        split_bf16<<<(n + 255) / 256, 256>>>((const float4*)Wo,
            (__nv_bfloat162*)Woh, (__nv_bfloat162*)Wol, n);
    }

    // merged QKV projection (fused RoPE/scale/split epilogue)
    qkv_gemm<<<dim3(24, 32), 256, SMEM_DYN>>>(Xh, Xl,
        Wqh, Wql, Wkh, Wkl, Wvh, Wvl,
        Qbh, Qbl, Kbh, Kbl, Vbh, Vbl);

    // MMA flash attention (causal), outputs bf16 hi/lo
    flash_mma<<<dim3(SS / 128, HQ, BB), 256, FSMEM>>>(Qbh, Qbl, Kbh, Kbl, Vbh, Vbl, Oh, Ol);

    // output projection -> fp32 result
    wo_gemm<<<dim3(16, 32), 256, SMEM_DYN>>>(Oh, Ol, Woh, Wol, out);
}